// round 13
// baseline (speedup 1.0000x reference)
#include <cuda_runtime.h>
#include <cuda_bf16.h>
#include <math.h>

#define NEG 0.01f
typedef unsigned long long ull;

// ---------------- packed f32x2 helpers (scalar conv path) ----------------
__device__ __forceinline__ ull pk2(float lo, float hi) {
    ull r; asm("mov.b64 %0,{%1,%2};" : "=l"(r) : "f"(lo), "f"(hi)); return r;
}
__device__ __forceinline__ void upk2(ull v, float& lo, float& hi) {
    asm("mov.b64 {%0,%1},%2;" : "=f"(lo), "=f"(hi) : "l"(v));
}
__device__ __forceinline__ ull ffma2(ull a, ull b, ull c) {
    ull d; asm("fma.rn.f32x2 %0,%1,%2,%3;" : "=l"(d) : "l"(a), "l"(b), "l"(c)); return d;
}

// ---------------- bf16 hi/lo split ----------------
__device__ __forceinline__ void split_bf16(float v, unsigned& h, unsigned& l) {
    __nv_bfloat16 hb = __float2bfloat16(v);
    float r = v - __bfloat162float(hb);
    __nv_bfloat16 lb = __float2bfloat16(r);
    h = (unsigned)__bfloat16_as_ushort(hb);
    l = (unsigned)__bfloat16_as_ushort(lb);
}

__device__ __forceinline__ void mma16816(float* c, unsigned a0, unsigned a1, unsigned a2, unsigned a3,
                                         unsigned b0, unsigned b1) {
    asm volatile("mma.sync.aligned.m16n8k16.row.col.f32.bf16.bf16.f32 "
        "{%0,%1,%2,%3}, {%4,%5,%6,%7}, {%8,%9}, {%0,%1,%2,%3};"
        : "+f"(c[0]), "+f"(c[1]), "+f"(c[2]), "+f"(c[3])
        : "r"(a0), "r"(a1), "r"(a2), "r"(a3), "r"(b0), "r"(b1));
}

// ---------------- scratch ----------------
__device__ unsigned g_bufA[64L*256*2048];   // A: hi @0, lo @PL_A
__device__ unsigned g_bufB[64L*256*1024];   // Bf planes / float flut-pvc scratch
__device__ unsigned g_bufP[64L*256*1024];   // P planes ping
__device__ float    g_bufC[64L*256*1024];   // conv0 packed input planes / P planes pong
__device__ float    g_qkv [64L*768*64];
__device__ unsigned g_att [64L*256*64];     // ATT planes
__device__ float    g_hm  [64L*256*64];
__device__ float g_xmain[64*256];
__device__ float g_fvec[64*4096];
__device__ float g_pvec[64*2048];
__device__ float g_f2[64*64];
__device__ float g_p2[64*32];
__device__ float g_freq[64*32];
__device__ float2 g_tw[4096];
__device__ float g_bn[8192];
__device__ float g_wT[4096];             // scalar-path weights (flut/pvc)
__device__ unsigned g_wf[6549504];       // mma fragment weights (hi/lo bf16)

#define PL_A   (64L*128*2048)
#define PL_B   (64L*128*1024)
#define PL_P   (64L*128*1024)
#define PL_ATT (64L*128*64)
#define PL_X   (64L*8*4096)

#define O_FLUT    0L
#define O_PVC     960L

#define WF_RC1    0L
#define WF_RC2    2949120L
#define WF_RID    5898240L
#define WF_MHAIN  6225920L
#define WF_MHAOUT 6422528L
#define WF_CONV0  6488064L

// ---------------- BN folding ----------------
__global__ void prep_kernel(const float* __restrict__ bn0,
                            const float* __restrict__ rbn1,
                            const float* __restrict__ rbn2,
                            const float* __restrict__ fbn, const float* __restrict__ fb,
                            const float* __restrict__ pbn, const float* __restrict__ pb)
{
    int c = threadIdx.x;
    if (c < 256) {
        {
            float g = bn0[c], b = bn0[256+c], m = bn0[512+c], v = bn0[768+c];
            float s = g * rsqrtf(v + 1e-5f);
            g_bn[c] = s; g_bn[256+c] = b - m*s;
        }
        for (int i = 0; i < 5; i++) {
            const float* p1 = rbn1 + i*1024;
            float g = p1[c], b = p1[256+c], m = p1[512+c], v = p1[768+c];
            float s = g * rsqrtf(v + 1e-5f);
            g_bn[512 + i*256 + c] = s; g_bn[1792 + i*256 + c] = b - m*s;
            const float* p2 = rbn2 + i*1024;
            g = p2[c]; b = p2[256+c]; m = p2[512+c]; v = p2[768+c];
            s = g * rsqrtf(v + 1e-5f);
            g_bn[3072 + i*256 + c] = s; g_bn[4352 + i*256 + c] = b - m*s;
        }
    }
    if (c < 64) {
        float g = fbn[c], b = fbn[64+c], m = fbn[128+c], v = fbn[192+c];
        float s = g * rsqrtf(v + 1e-5f);
        g_bn[5632+c] = s; g_bn[5696+c] = (fb[c] - m)*s + b;
        g = pbn[c]; b = pbn[64+c]; m = pbn[128+c]; v = pbn[192+c];
        s = g * rsqrtf(v + 1e-5f);
        g_bn[5760+c] = s; g_bn[5824+c] = (pb[c] - m)*s + b;
    }
}

// ---------------- pack x for conv0: pair planes, 12->16 padded channels ----------------
__global__ void pack_x_kernel(const float* __restrict__ x,
                              unsigned* __restrict__ xhi, unsigned* __restrict__ xlo)
{
    long i = (long)blockIdx.x*256 + threadIdx.x;
    if (i >= 64L*8*4096) return;
    int t = (int)(i & 4095);
    long r = i >> 12;
    int p = (int)(r & 7);
    int b = (int)(r >> 3);
    int c0 = 2*p, c1 = 2*p + 1;
    float v0 = (c0 < 12) ? x[((long)b*12 + c0)*4096 + t] : 0.f;
    float v1 = (c1 < 12) ? x[((long)b*12 + c1)*4096 + t] : 0.f;
    unsigned h0, l0, h1, l1;
    split_bf16(v0, h0, l0);
    split_bf16(v1, h1, l1);
    xhi[i] = h0 | (h1 << 16);
    xlo[i] = l0 | (l1 << 16);
}

// ---------------- weight transpose (scalar conv path) ----------------
__global__ void wtrans_kernel(const float* __restrict__ src, float* __restrict__ dst,
                              int CI, int KW, long total)
{
    long i = (long)blockIdx.x*256 + threadIdx.x;
    if (i >= total) return;
    int co64 = (int)(i & 63);
    long r = i >> 6;
    int k = (int)(r % KW); r /= KW;
    int ci = (int)(r % CI);
    long ct = r / CI;
    long co = ct*64 + co64;
    dst[i] = src[(co*CI + ci)*KW + k];
}

// ---------------- weight -> mma fragment (hi/lo bf16), CIsrc-padded ----------------
__global__ void wfrag_kernel(const float* __restrict__ src, unsigned* __restrict__ dst,
                             int CIsrc, int KW, int NCH, long total)
{
    long i = (long)blockIdx.x*256 + threadIdx.x;
    if (i >= total) return;
    int r    = (int)(i & 3);
    int lane = (int)((i >> 2) & 31);
    long rest = i >> 7;
    int k  = (int)(rest % KW); rest /= KW;
    int ch = (int)(rest % NCH);
    long ct = rest / NCH;
    int row = lane >> 2;
    int col = (lane & 3) * 2;
    if (r & 1) row += 8;
    if (r >= 2) col += 8;
    long co = ct*16 + row;
    int ci = ch*16 + col;
    float w0 = (ci     < CIsrc) ? src[(co*CIsrc + ci    )*KW + k] : 0.f;
    float w1 = (ci + 1 < CIsrc) ? src[(co*CIsrc + ci + 1)*KW + k] : 0.f;
    unsigned h0, l0, h1, l1;
    split_bf16(w0, h0, l0);
    split_bf16(w1, h1, l1);
    long base = (((ct*NCH + ch)*KW + k)*32 + lane)*8;
    dst[base + r]     = h0 | (h1 << 16);
    dst[base + 4 + r] = l0 | (l1 << 16);
}

// ---------------- tensor-core conv1d (bf16 split planes, fp32 acc) ----------------
template<int KW, int STRIDE, int TT, int CB2>
__global__ void __launch_bounds__(256, 2) conv_mma(
    const unsigned* __restrict__ wf,
    const unsigned* __restrict__ inHi, const unsigned* __restrict__ inLo,
    const float* __restrict__ scale, const float* __restrict__ bias,
    const float* __restrict__ addb,
    float* __restrict__ outF,
    unsigned* __restrict__ outHi, unsigned* __restrict__ outLo,
    unsigned* __restrict__ poolHi, unsigned* __restrict__ poolLo,
    int CI, int CO, int Lin, int Lout, int pad, int dorelu, long inBS)
{
    constexpr int WIN = TT*STRIDE + KW - 1;
    constexpr int NN  = TT / 16;
    constexpr int W   = CB2*10;
    __shared__ __align__(16) unsigned sHi[2][WIN][W];
    __shared__ __align__(16) unsigned sLo[2][WIN][W];

    const int tid  = threadIdx.x;
    const int lane = tid & 31;
    const int wid  = tid >> 5;
    const int wco  = wid & 3;
    const int wt   = wid >> 2;
    const int t0   = blockIdx.x * TT;
    const int co0  = blockIdx.y * 128;
    const int b    = blockIdx.z;
    const int NCH  = CI >> 4;
    const int nst  = NCH / CB2;
    const long ct0 = (co0 >> 4) + wco*2;
    const unsigned* inHib = inHi + (long)b * inBS;
    const unsigned* inLob = inLo + (long)b * inBS;

    float acc[2][NN][4] = {};

    auto stage = [&](int buf, int grp) {
        int cp0 = grp * CB2 * 8;
        for (int idx = tid; idx < CB2*8*WIN; idx += 256) {
            int c2 = idx / (8*WIN);
            int rem = idx - c2*8*WIN;
            int pr = rem / WIN, pos = rem - pr*WIN;
            int j = c2*10 + ((pr < 4) ? (2*pr) : (2*(pr-4)+1));
            int g = t0*STRIDE - pad + pos;
            unsigned vh = 0, vl = 0;
            if (g >= 0 && g < Lin) {
                long gi = (long)(cp0 + c2*8 + pr)*Lin + g;
                vh = __ldg(&inHib[gi]);
                vl = __ldg(&inLob[gi]);
            }
            sHi[buf][pos][j] = vh;
            sLo[buf][pos][j] = vl;
        }
    };

    stage(0, 0);
    __syncthreads();
    for (int s = 0; s < nst; s++) {
        int cur = s & 1;
        if (s + 1 < nst) stage(cur ^ 1, s + 1);
        #pragma unroll
        for (int c2 = 0; c2 < CB2; c2++) {
            int ch = s*CB2 + c2;
            #pragma unroll
            for (int k = 0; k < KW; k++) {
                const uint4* af0 = (const uint4*)(wf + (((ct0*NCH + ch)*KW + k) << 8) + (lane << 3));
                const uint4* af1 = (const uint4*)(wf + ((((ct0+1)*NCH + ch)*KW + k) << 8) + (lane << 3));
                uint4 ahi0 = af0[0], alo0 = af0[1];
                uint4 ahi1 = af1[0], alo1 = af1[1];
                #pragma unroll
                for (int n = 0; n < NN; n++) {
                    int tl = wt*(TT/2) + n*8 + (lane >> 2);
                    int pos = tl*STRIDE + k;
                    int j2 = c2*10 + (lane & 3)*2;
                    uint2 bh = *(const uint2*)&sHi[cur][pos][j2];
                    uint2 bl = *(const uint2*)&sLo[cur][pos][j2];
                    mma16816(acc[0][n], ahi0.x, ahi0.y, ahi0.z, ahi0.w, bh.x, bh.y);
                    mma16816(acc[0][n], alo0.x, alo0.y, alo0.z, alo0.w, bh.x, bh.y);
                    mma16816(acc[0][n], ahi0.x, ahi0.y, ahi0.z, ahi0.w, bl.x, bl.y);
                    mma16816(acc[1][n], ahi1.x, ahi1.y, ahi1.z, ahi1.w, bh.x, bh.y);
                    mma16816(acc[1][n], alo1.x, alo1.y, alo1.z, alo1.w, bh.x, bh.y);
                    mma16816(acc[1][n], ahi1.x, ahi1.y, ahi1.z, ahi1.w, bl.x, bl.y);
                }
            }
        }
        __syncthreads();
    }

    #pragma unroll
    for (int q = 0; q < 2; q++) {
        #pragma unroll
        for (int n = 0; n < NN; n++) {
            int t = t0 + wt*(TT/2) + n*8 + (lane & 3)*2;
            #pragma unroll
            for (int h = 0; h < 2; h++) {
                int co = co0 + wco*32 + q*16 + (lane >> 2) + h*8;
                float sc = scale ? scale[co] : 1.f;
                float bb = bias  ? bias[co]  : 0.f;
                float x0 = acc[q][n][2*h]   * sc + bb;
                float x1 = acc[q][n][2*h+1] * sc + bb;
                if (dorelu) {
                    x0 = x0 >= 0.f ? x0 : NEG*x0;
                    x1 = x1 >= 0.f ? x1 : NEG*x1;
                }
                if (addb) {
                    long obase = ((long)b*CO + co) * Lout + t;
                    float2 a = *(const float2*)&addb[obase];
                    x0 += a.x; x1 += a.y;
                }
                if (outF) {
                    long obase = ((long)b*CO + co) * Lout + t;
                    *(float2*)&outF[obase] = make_float2(x0, x1);
                }
                if (outHi) {
                    float p0 = __shfl_xor_sync(0xffffffffu, x0, 4);
                    float p1 = __shfl_xor_sync(0xffffffffu, x1, 4);
                    if (!(lane & 4)) {
                        unsigned a0h, a0l, b0h, b0l, a1h, a1l, b1h, b1l;
                        split_bf16(x0, a0h, a0l); split_bf16(p0, b0h, b0l);
                        split_bf16(x1, a1h, a1l); split_bf16(p1, b1h, b1l);
                        long pb = ((long)b*(CO >> 1) + (co >> 1))*Lout + t;
                        *(uint2*)&outHi[pb] = make_uint2(a0h | (b0h << 16), a1h | (b1h << 16));
                        *(uint2*)&outLo[pb] = make_uint2(a0l | (b0l << 16), a1l | (b1l << 16));
                    }
                }
                if (poolHi) {
                    float avg = 0.5f*(x0 + x1);
                    float pav = __shfl_xor_sync(0xffffffffu, avg, 4);
                    if (!(lane & 4)) {
                        unsigned ah, al, ph, pl;
                        split_bf16(avg, ah, al); split_bf16(pav, ph, pl);
                        long pb = ((long)b*(CO >> 1) + (co >> 1))*(Lout >> 1) + (t >> 1);
                        poolHi[pb] = ah | (ph << 16);
                        poolLo[pb] = al | (pl << 16);
                    }
                }
            }
        }
    }
}

template<int KW, int STRIDE, int TT, int CB2>
static void launch_conv(dim3 grid,
    const unsigned* wf, const unsigned* inHi, const unsigned* inLo,
    const float* scale, const float* bias, const float* addb,
    float* outF, unsigned* outHi, unsigned* outLo, unsigned* poolHi, unsigned* poolLo,
    int CI, int CO, int Lin, int Lout, int pad, int dorelu, long inBS)
{
    conv_mma<KW,STRIDE,TT,CB2><<<grid, 256>>>(wf, inHi, inLo, scale, bias, addb,
        outF, outHi, outLo, poolHi, poolLo, CI, CO, Lin, Lout, pad, dorelu, inBS);
}

// ---------------- fused rc2 (KW=9, s=1) + rid (KW=1): out = relu(bn(conv9(B))) + conv1(P) ----------------
template<int TT, int CB2>
__global__ void __launch_bounds__(256, 2) conv_mma_fused(
    const unsigned* __restrict__ wf9, const unsigned* __restrict__ wf1,
    const unsigned* __restrict__ bHi, const unsigned* __restrict__ bLo,
    const unsigned* __restrict__ pHi, const unsigned* __restrict__ pLo,
    const float* __restrict__ scale, const float* __restrict__ bias,
    unsigned* __restrict__ outHi, unsigned* __restrict__ outLo,
    unsigned* __restrict__ poolHi, unsigned* __restrict__ poolLo,
    int Lh, long inBS)
{
    constexpr int WIN = TT + 8;     // KW=9, pad=4
    constexpr int NN  = TT / 16;
    constexpr int W   = CB2*10;
    __shared__ __align__(16) unsigned sBH[2][WIN][W], sBL[2][WIN][W];
    __shared__ __align__(16) unsigned sPH[2][TT][W],  sPL[2][TT][W];

    const int tid  = threadIdx.x;
    const int lane = tid & 31;
    const int wid  = tid >> 5;
    const int wco  = wid & 3;
    const int wt   = wid >> 2;
    const int t0   = blockIdx.x * TT;
    const int co0  = blockIdx.y * 128;
    const int b    = blockIdx.z;
    const int NCH  = 16;            // CI=256
    const int nst  = NCH / CB2;
    const long ct0 = (co0 >> 4) + wco*2;
    const unsigned* bHib = bHi + (long)b * inBS;
    const unsigned* bLob = bLo + (long)b * inBS;
    const unsigned* pHib = pHi + (long)b * inBS;
    const unsigned* pLob = pLo + (long)b * inBS;

    float acc9[2][NN][4] = {};
    float acc1[2][NN][4] = {};

    auto stage = [&](int buf, int grp) {
        int cp0 = grp * CB2 * 8;
        for (int idx = tid; idx < CB2*8*WIN; idx += 256) {
            int c2 = idx / (8*WIN);
            int rem = idx - c2*8*WIN;
            int pr = rem / WIN, pos = rem - pr*WIN;
            int j = c2*10 + ((pr < 4) ? (2*pr) : (2*(pr-4)+1));
            long row = (long)(cp0 + c2*8 + pr)*Lh;
            int g = t0 - 4 + pos;
            unsigned vh = 0, vl = 0;
            if (g >= 0 && g < Lh) {
                vh = __ldg(&bHib[row + g]);
                vl = __ldg(&bLob[row + g]);
            }
            sBH[buf][pos][j] = vh;
            sBL[buf][pos][j] = vl;
            if (pos < TT) {
                sPH[buf][pos][j] = __ldg(&pHib[row + t0 + pos]);
                sPL[buf][pos][j] = __ldg(&pLob[row + t0 + pos]);
            }
        }
    };

    stage(0, 0);
    __syncthreads();
    for (int s = 0; s < nst; s++) {
        int cur = s & 1;
        if (s + 1 < nst) stage(cur ^ 1, s + 1);
        #pragma unroll
        for (int c2 = 0; c2 < CB2; c2++) {
            int ch = s*CB2 + c2;
            #pragma unroll
            for (int k = 0; k < 9; k++) {
                const uint4* af0 = (const uint4*)(wf9 + (((ct0*NCH + ch)*9 + k) << 8) + (lane << 3));
                const uint4* af1 = (const uint4*)(wf9 + ((((ct0+1)*NCH + ch)*9 + k) << 8) + (lane << 3));
                uint4 ahi0 = af0[0], alo0 = af0[1];
                uint4 ahi1 = af1[0], alo1 = af1[1];
                #pragma unroll
                for (int n = 0; n < NN; n++) {
                    int tl = wt*(TT/2) + n*8 + (lane >> 2);
                    int pos = tl + k;
                    int j2 = c2*10 + (lane & 3)*2;
                    uint2 bh = *(const uint2*)&sBH[cur][pos][j2];
                    uint2 bl = *(const uint2*)&sBL[cur][pos][j2];
                    mma16816(acc9[0][n], ahi0.x, ahi0.y, ahi0.z, ahi0.w, bh.x, bh.y);
                    mma16816(acc9[0][n], alo0.x, alo0.y, alo0.z, alo0.w, bh.x, bh.y);
                    mma16816(acc9[0][n], ahi0.x, ahi0.y, ahi0.z, ahi0.w, bl.x, bl.y);
                    mma16816(acc9[1][n], ahi1.x, ahi1.y, ahi1.z, ahi1.w, bh.x, bh.y);
                    mma16816(acc9[1][n], alo1.x, alo1.y, alo1.z, alo1.w, bh.x, bh.y);
                    mma16816(acc9[1][n], ahi1.x, ahi1.y, ahi1.z, ahi1.w, bl.x, bl.y);
                }
            }
            {
                const uint4* af0 = (const uint4*)(wf1 + (((ct0*NCH + ch)) << 8) + (lane << 3));
                const uint4* af1 = (const uint4*)(wf1 + ((((ct0+1)*NCH + ch)) << 8) + (lane << 3));
                uint4 ahi0 = af0[0], alo0 = af0[1];
                uint4 ahi1 = af1[0], alo1 = af1[1];
                #pragma unroll
                for (int n = 0; n < NN; n++) {
                    int pos = wt*(TT/2) + n*8 + (lane >> 2);
                    int j2 = c2*10 + (lane & 3)*2;
                    uint2 bh = *(const uint2*)&sPH[cur][pos][j2];
                    uint2 bl = *(const uint2*)&sPL[cur][pos][j2];
                    mma16816(acc1[0][n], ahi0.x, ahi0.y, ahi0.z, ahi0.w, bh.x, bh.y);
                    mma16816(acc1[0][n], alo0.x, alo0.y, alo0.z, alo0.w, bh.x, bh.y);
                    mma16816(acc1[0][n], ahi0.x, ahi0.y, ahi0.z, ahi0.w, bl.x, bl.y);
                    mma16816(acc1[1][n], ahi1.x, ahi1.y, ahi1.z, ahi1.w, bh.x, bh.y);
                    mma16816(acc1[1][n], alo1.x, alo1.y, alo1.z, alo1.w, bh.x, bh.y);
                    mma16816(acc1[1][n], ahi1.x, ahi1.y, ahi1.z, ahi1.w, bl.x, bl.y);
                }
            }
        }
        __syncthreads();
    }

    #pragma unroll
    for (int q = 0; q < 2; q++) {
        #pragma unroll
        for (int n = 0; n < NN; n++) {
            int t = t0 + wt*(TT/2) + n*8 + (lane & 3)*2;
            #pragma unroll
            for (int h = 0; h < 2; h++) {
                int co = co0 + wco*32 + q*16 + (lane >> 2) + h*8;
                float sc = scale[co];
                float bb = bias[co];
                float x0 = acc9[q][n][2*h]   * sc + bb;
                float x1 = acc9[q][n][2*h+1] * sc + bb;
                x0 = x0 >= 0.f ? x0 : NEG*x0;
                x1 = x1 >= 0.f ? x1 : NEG*x1;
                x0 += acc1[q][n][2*h];
                x1 += acc1[q][n][2*h+1];
                float p0 = __shfl_xor_sync(0xffffffffu, x0, 4);
                float p1 = __shfl_xor_sync(0xffffffffu, x1, 4);
                float avg = 0.5f*(x0 + x1);
                float pav = __shfl_xor_sync(0xffffffffu, avg, 4);
                if (!(lane & 4)) {
                    unsigned a0h, a0l, b0h, b0l, a1h, a1l, b1h, b1l;
                    split_bf16(x0, a0h, a0l); split_bf16(p0, b0h, b0l);
                    split_bf16(x1, a1h, a1l); split_bf16(p1, b1h, b1l);
                    long pb = ((long)b*128 + (co >> 1))*Lh + t;
                    *(uint2*)&outHi[pb] = make_uint2(a0h | (b0h << 16), a1h | (b1h << 16));
                    *(uint2*)&outLo[pb] = make_uint2(a0l | (b0l << 16), a1l | (b1l << 16));
                    unsigned ah, al, ph, pl;
                    split_bf16(avg, ah, al); split_bf16(pav, ph, pl);
                    long qb = ((long)b*128 + (co >> 1))*(Lh >> 1) + (t >> 1);
                    poolHi[qb] = ah | (ph << 16);
                    poolLo[qb] = al | (pl << 16);
                }
            }
        }
    }
}

// ---------------- scalar implicit-GEMM conv1d (CI=1 layers) ----------------
template<int KW, int STRIDE, int CB>
__global__ void __launch_bounds__(256, 2) conv_gemm(
    const float* __restrict__ wT, const float* __restrict__ in,
    const float* __restrict__ scale, const float* __restrict__ bias,
    float* __restrict__ out,
    int CI, int CO, int Lin, int Lout, int pad, int dorelu, long inBS)
{
    constexpr int WIN  = 64*STRIDE + KW - 1;
    constexpr int WINP = (WIN + 11) & ~3;
    constexpr int RW   = 3*STRIDE + KW;
    constexpr int NV   = (RW + 3) / 4;
    __shared__ __align__(16) float sW[2][CB*KW*64];
    __shared__ __align__(16) float sIn[2][CB][WINP];

    const int tid = threadIdx.x;
    const int tx = tid & 15, ty = tid >> 4;
    const int t0 = blockIdx.x * 64, co0 = blockIdx.y * 64;
    const int b  = blockIdx.z;
    const float* inb = in + (long)b * inBS;
    const long wstride = (long)KW * 64;
    const float* wbase = wT + (long)blockIdx.y * CI * wstride;

    ull acc01[4], acc23[4];
    #pragma unroll
    for (int j = 0; j < 4; j++) { acc01[j] = 0ull; acc23[j] = 0ull; }

    const int nst = CI / CB;
    auto stage = [&](int buf, int cib) {
        const float4* ws = (const float4*)(wbase + (long)cib * wstride);
        float4* wd = (float4*)sW[buf];
        for (int idx = tid; idx < CB*KW*16; idx += 256) wd[idx] = ws[idx];
        for (int idx = tid; idx < CB*WIN; idx += 256) {
            int c = idx / WIN, w = idx - c*WIN;
            int g = t0*STRIDE - pad + w;
            sIn[buf][c][w] = (g >= 0 && g < Lin) ? __ldg(&inb[(long)(cib+c)*Lin + g]) : 0.f;
        }
    };

    stage(0, 0);
    __syncthreads();
    for (int s = 0; s < nst; s++) {
        int cur = s & 1;
        if (s + 1 < nst) stage(cur ^ 1, (s + 1) * CB);
        #pragma unroll
        for (int c = 0; c < CB; c++) {
            float4 wv4[NV];
            const float4* ip = (const float4*)&sIn[cur][c][tx*4*STRIDE];
            #pragma unroll
            for (int v = 0; v < NV; v++) wv4[v] = ip[v];
            const float* wfp = (const float*)wv4;
            ull bc[RW];
            #pragma unroll
            for (int m = 0; m < RW; m++) bc[m] = pk2(wfp[m], wfp[m]);
            const float* wrow = sW[cur] + c*KW*64 + ty*4;
            #pragma unroll
            for (int k = 0; k < KW; k++) {
                ulonglong2 wv = *(const ulonglong2*)(wrow + k*64);
                #pragma unroll
                for (int j = 0; j < 4; j++) {
                    acc01[j] = ffma2(wv.x, bc[j*STRIDE + k], acc01[j]);
                    acc23[j] = ffma2(wv.y, bc[j*STRIDE + k], acc23[j]);
                }
            }
        }
        __syncthreads();
    }

    float r[4][4];
    #pragma unroll
    for (int j = 0; j < 4; j++) { upk2(acc01[j], r[0][j], r[1][j]); upk2(acc23[j], r[2][j], r[3][j]); }
    #pragma unroll
    for (int i = 0; i < 4; i++) {
        int co = co0 + ty*4 + i;
        float sc = scale ? scale[co] : 1.f;
        float bb = bias  ? bias[co]  : 0.f;
        long obase = ((long)b*CO + co) * Lout + t0 + tx*4;
        float4 v;
        v.x = r[i][0]*sc + bb; v.y = r[i][1]*sc + bb;
        v.z = r[i][2]*sc + bb; v.w = r[i][3]*sc + bb;
        if (dorelu) {
            v.x = v.x >= 0.f ? v.x : NEG*v.x; v.y = v.y >= 0.f ? v.y : NEG*v.y;
            v.z = v.z >= 0.f ? v.z : NEG*v.z; v.w = v.w >= 0.f ? v.w : NEG*v.w;
        }
        *(float4*)&out[obase] = v;
    }
}

// ---------------- attention per (batch, head): writes ATT pair planes ----------------
__global__ void __launch_bounds__(128) attn_kernel(const float* __restrict__ qkv,
                                                   unsigned* __restrict__ ohi,
                                                   unsigned* __restrict__ olo)
{
    __shared__ float q[32][64], kk[32][64], vv[32][64];
    __shared__ float att[64][65];
    int bh = blockIdx.x; int b = bh >> 3, h = bh & 7;
    const float* base = qkv + (long)b*768*64 + (long)h*32*64;
    int tid = threadIdx.x;
    for (int idx = tid; idx < 2048; idx += 128) {
        int d = idx >> 6, s = idx & 63;
        q [d][s] = base[d*64 + s];
        kk[d][s] = base[256*64 + d*64 + s];
        vv[d][s] = base[512*64 + d*64 + s];
    }
    __syncthreads();
    for (int e = tid; e < 4096; e += 128) {
        int qs = e >> 6, ks = e & 63;
        float s = 0.f;
        #pragma unroll
        for (int d = 0; d < 32; d++) s = fmaf(q[d][qs], kk[d][ks], s);
        att[qs][ks] = s * 0.17677669529663687f;
    }
    __syncthreads();
    if (tid < 64) {
        float m = -1e30f;
        for (int ks = 0; ks < 64; ks++) m = fmaxf(m, att[tid][ks]);
        float sum = 0.f;
        for (int ks = 0; ks < 64; ks++) { float e = expf(att[tid][ks] - m); att[tid][ks] = e; sum += e; }
        float inv = 1.f / sum;
        for (int ks = 0; ks < 64; ks++) att[tid][ks] *= inv;
    }
    __syncthreads();
    for (int e = tid; e < 1024; e += 128) {
        int m = e >> 6, qs = e & 63;
        float s0 = 0.f, s1 = 0.f;
        #pragma unroll
        for (int ks = 0; ks < 64; ks++) {
            float a = att[qs][ks];
            s0 = fmaf(a, vv[2*m][ks],   s0);
            s1 = fmaf(a, vv[2*m+1][ks], s1);
        }
        unsigned h0, l0, h1, l1;
        split_bf16(s0, h0, l0);
        split_bf16(s1, h1, l1);
        long idx = ((long)b*128 + h*16 + m)*64 + qs;
        ohi[idx] = h0 | (h1 << 16);
        olo[idx] = l0 | (l1 << 16);
    }
}

__global__ void max_t_kernel(const float* __restrict__ in, float* __restrict__ out)
{
    int b = blockIdx.x, c = threadIdx.x;
    const float* r = in + ((long)b*256 + c) * 64;
    float m = r[0];
    #pragma unroll
    for (int t = 1; t < 64; t++) m = fmaxf(m, r[t]);
    out[b*256 + c] = m;
}

__global__ void group_max_kernel(const float* __restrict__ in, float* __restrict__ out, int GS)
{
    int row = blockIdx.x; int g = threadIdx.x; int G = blockDim.x;
    const float* r = in + (long)row*G*GS + (long)g*GS;
    float m = r[0];
    for (int j = 1; j < GS; j++) m = fmaxf(m, r[j]);
    out[(long)row*G + g] = m;
}

// ---------------- dense: one warp per (batch, output) ----------------
__global__ void __launch_bounds__(256) dense_kernel(const float* __restrict__ in,
                                                    const float* __restrict__ w,
                                                    const float* __restrict__ bias,
                                                    float* __restrict__ out,
                                                    int IN, int OUT, int dorelu)
{
    int wid = threadIdx.x >> 5, lane = threadIdx.x & 31;
    int gid = blockIdx.x*8 + wid;
    int b = gid / OUT, o = gid - b*OUT;
    if (b >= 64) return;
    const float* iv = in + (long)b*IN;
    const float* wr = w + (long)o*IN;
    float s = 0.f;
    for (int i = lane; i < IN; i += 32) s = fmaf(iv[i], wr[i], s);
    #pragma unroll
    for (int off = 16; off > 0; off >>= 1) s += __shfl_down_sync(0xffffffffu, s, off);
    if (lane == 0) {
        if (bias) s += bias[o];
        if (dorelu) s = (s >= 0.f) ? s : NEG*s;
        out[b*OUT + o] = s;
    }
}

__global__ void twiddle_kernel()
{
    int i = blockIdx.x*256 + threadIdx.x;
    if (i < 4096) {
        double a = -2.0 * 3.14159265358979323846 * (double)i / 4096.0;
        g_tw[i] = make_float2((float)cos(a), (float)sin(a));
    }
}

__global__ void __launch_bounds__(256) fft_freq_kernel(const float* __restrict__ x,
                                                       const float* __restrict__ fw,
                                                       const float* __restrict__ fb,
                                                       float* __restrict__ out)
{
    __shared__ float2 stw[4096];
    __shared__ float smag[256];
    __shared__ float sred[256];
    int b = blockIdx.x, tid = threadIdx.x;
    for (int i = tid; i < 4096; i += 256) stw[i] = g_tw[i];
    const float* xr = x + ((long)b*12 + 1) * 4096;
    __syncthreads();
    int k = 50 + tid;
    float re0 = 0.f, im0 = 0.f, re1 = 0.f, im1 = 0.f;
    for (int n = 0; n < 4096; n += 4) {
        float4 xv = *(const float4*)&xr[n];
        int i0 = (k*n) & 4095;
        int i1 = (i0 + k) & 4095;
        int i2 = (i0 + 2*k) & 4095;
        int i3 = (i0 + 3*k) & 4095;
        float2 c0 = stw[i0], c1 = stw[i1], c2 = stw[i2], c3 = stw[i3];
        re0 = fmaf(xv.x, c0.x, re0); im0 = fmaf(xv.x, c0.y, im0);
        re1 = fmaf(xv.y, c1.x, re1); im1 = fmaf(xv.y, c1.y, im1);
        re0 = fmaf(xv.z, c2.x, re0); im0 = fmaf(xv.z, c2.y, im0);
        re1 = fmaf(xv.w, c3.x, re1); im1 = fmaf(xv.w, c3.y, im1);
    }
    float re = re0 + re1, im = im0 + im1;
    float mag = sqrtf(re*re + im*im);
    smag[tid] = mag; sred[tid] = mag;
    __syncthreads();
    for (int s = 128; s > 0; s >>= 1) {
        if (tid < s) sred[tid] = fmaxf(sred[tid], sred[tid+s]);
        __syncthreads();
    }
    float mx = sred[0];
    smag[tid] = (mx > 0.f) ? mag/mx : mag;
    __syncthreads();
    if (tid < 32) {
        float s = fb[tid];
        const float* wr = fw + tid*256;
        for (int j = 0; j < 256; j++) s = fmaf(smag[j], wr[j], s);
        out[b*32 + tid] = (s >= 0.f) ? s : NEG*s;
    }
}

__global__ void final_kernel(const float* __restrict__ xm, const float* __restrict__ l,
                             const float* __restrict__ fq, const float* __restrict__ f2,
                             const float* __restrict__ p2, const float* __restrict__ fcw,
                             const float* __restrict__ fcb, float* __restrict__ out)
{
    __shared__ float comb[396];
    int b = blockIdx.x, tid = threadIdx.x;
    for (int i = tid; i < 256; i += 128) comb[i] = xm[b*256 + i];
    if (tid < 12) comb[256 + tid] = l[b*12 + tid];
    if (tid < 32) comb[268 + tid] = fq[b*32 + tid];
    if (tid < 64) comb[300 + tid] = f2[b*64 + tid];
    if (tid < 32) comb[364 + tid] = p2[b*32 + tid];
    __syncthreads();
    if (tid < 27) {
        float s = fcb[tid];
        const float* wr = fcw + tid*396;
        for (int j = 0; j < 396; j++) s = fmaf(comb[j], wr[j], s);
        out[b*27 + tid] = s;
        out[64*27 + b*27 + tid] = 1.f / (1.f + expf(-s));
    }
}

// ---------------- host launch ----------------
extern "C" void kernel_launch(void* const* d_in, const int* in_sizes, int n_in,
                              void* d_out, int out_size)
{
    (void)in_sizes; (void)n_in; (void)out_size;
    const float* x      = (const float*)d_in[0];
    const float* l      = (const float*)d_in[1];
    const float* conv_w = (const float*)d_in[2];
    const float* bn0    = (const float*)d_in[3];
    const float* rc1    = (const float*)d_in[4];
    const float* rbn1   = (const float*)d_in[5];
    const float* rc2    = (const float*)d_in[6];
    const float* rbn2   = (const float*)d_in[7];
    const float* rid    = (const float*)d_in[8];
    const float* miw    = (const float*)d_in[9];
    const float* mib    = (const float*)d_in[10];
    const float* mow    = (const float*)d_in[11];
    const float* mob    = (const float*)d_in[12];
    const float* fw     = (const float*)d_in[13];
    const float* fbv    = (const float*)d_in[14];
    const float* fbn    = (const float*)d_in[15];
    const float* pw     = (const float*)d_in[16];
    const float* pbv    = (const float*)d_in[17];
    const float* pbn    = (const float*)d_in[18];
    const float* wflut2 = (const float*)d_in[19];
    const float* wpvc2  = (const float*)d_in[20];
    const float* freqw  = (const float*)d_in[21];
    const float* freqb  = (const float*)d_in[22];
    const float* fcw    = (const float*)d_in[23];
    const float* fcb    = (const float*)d_in[24];

    unsigned *A, *Bf, *P0, *ATT, *WF;
    float *C, *QKV, *HM, *XM, *FV, *PV, *F2, *P2, *FQ, *BN, *WT;
    cudaGetSymbolAddress((void**)&A,   g_bufA);
    cudaGetSymbolAddress((void**)&Bf,  g_bufB);
    cudaGetSymbolAddress((void**)&P0,  g_bufP);
    cudaGetSymbolAddress((void**)&C,   g_bufC);
    cudaGetSymbolAddress((void**)&QKV, g_qkv);
    cudaGetSymbolAddress((void**)&ATT, g_att);
    cudaGetSymbolAddress((void**)&HM,  g_hm);
    cudaGetSymbolAddress((void**)&XM,  g_xmain);
    cudaGetSymbolAddress((void**)&FV,  g_fvec);
    cudaGetSymbolAddress((void**)&PV,  g_pvec);
    cudaGetSymbolAddress((void**)&F2,  g_f2);
    cudaGetSymbolAddress((void**)&P2,  g_p2);
    cudaGetSymbolAddress((void**)&FQ,  g_freq);
    cudaGetSymbolAddress((void**)&BN,  g_bn);
    cudaGetSymbolAddress((void**)&WT,  g_wT);
    cudaGetSymbolAddress((void**)&WF,  g_wf);

    unsigned* P1 = (unsigned*)C;   // P pong (C region free after conv0 input staging)
    unsigned* XP = (unsigned*)C;   // conv0 packed input planes

    prep_kernel<<<1, 256>>>(bn0, rbn1, rbn2, fbn, fbv, pbn, pbv);
    twiddle_kernel<<<16, 256>>>();
    pack_x_kernel<<<8192, 256>>>(x, XP, XP + PL_X);

    auto wt = [&](const float* src, long off, int CO, int CI, int KW) {
        long tot = (long)CO*CI*KW;
        wtrans_kernel<<<(unsigned)((tot + 255)/256), 256>>>(src, WT + off, CI, KW, tot);
    };
    wt(fw, O_FLUT, 64, 1, 15);
    wt(pw, O_PVC,  64, 1, 9);

    auto wfp = [&](const float* src, long off, int CO, int CIsrc, int CIpad, int KW) {
        long tot = (long)(CO/16)*(CIpad/16)*KW*128;
        wfrag_kernel<<<(unsigned)((tot + 255)/256), 256>>>(src, WF + off, CIsrc, KW, CIpad/16, tot);
    };
    for (int i = 0; i < 5; i++) {
        wfp(rc1 + (long)i*256*256*9, WF_RC1 + (long)i*589824, 256, 256, 256, 9);
        wfp(rc2 + (long)i*256*256*9, WF_RC2 + (long)i*589824, 256, 256, 256, 9);
        wfp(rid + (long)i*256*256,   WF_RID + (long)i*65536,  256, 256, 256, 1);
    }
    wfp(miw,    WF_MHAIN,  768, 256, 256, 1);
    wfp(mow,    WF_MHAOUT, 256, 256, 256, 1);
    wfp(conv_w, WF_CONV0,  256,  12,  16, 15);

    // conv0: mma path -> A planes + pooled P planes (into P0)
    launch_conv<15,2,64,1>(dim3(32,2,64), WF+WF_CONV0, XP, XP + PL_X, BN+0, BN+256, nullptr,
                           nullptr, A, A + PL_A, P0, P0 + PL_P,
                           16, 256, 4096, 2048, 7, 1, 8L*4096);

    int L = 2048;
    for (int i = 0; i < 5; i++) {
        int Lh = L/2;
        unsigned* Pin  = (i & 1) ? P1 : P0;
        unsigned* Pout = (i & 1) ? P0 : P1;
        // rc1: A -> Bf
        if (Lh >= 256)
            launch_conv<9,2,128,1>(dim3(Lh/128,2,64), WF+WF_RC1 + (long)i*589824, A, A + PL_A,
                BN+512+i*256, BN+1792+i*256, nullptr, nullptr, Bf, Bf + PL_B, nullptr, nullptr,
                256, 256, L, Lh, 4, 1, 128L*L);
        else if (Lh == 128)
            launch_conv<9,2,64,1>(dim3(2,2,64), WF+WF_RC1 + (long)i*589824, A, A + PL_A,
                BN+512+i*256, BN+1792+i*256, nullptr, nullptr, Bf, Bf + PL_B, nullptr, nullptr,
                256, 256, L, Lh, 4, 1, 128L*L);
        else
            launch_conv<9,2,32,1>(dim3(2,2,64), WF+WF_RC1 + (long)i*589824, A, A + PL_A,
                BN+512+i*256, BN+1792+i*256, nullptr, nullptr, Bf, Bf + PL_B, nullptr, nullptr,
                256, 256, L, Lh, 4, 1, 128L*L);
        // fused rc2 + rid: (Bf, Pin) -> A + pooled Pout
        if (Lh >= 64)
            conv_mma_fused<64,2><<<dim3(Lh/64,2,64), 256>>>(
                WF+WF_RC2 + (long)i*589824, WF+WF_RID + (long)i*65536,
                Bf, Bf + PL_B, Pin, Pin + PL_P,
                BN+3072+i*256, BN+4352+i*256,
                A, A + PL_A, Pout, Pout + PL_P, Lh, 128L*Lh);
        else
            conv_mma_fused<32,2><<<dim3(Lh/32,2,64), 256>>>(
                WF+WF_RC2 + (long)i*589824, WF+WF_RID + (long)i*65536,
                Bf, Bf + PL_B, Pin, Pin + PL_P,
                BN+3072+i*256, BN+4352+i*256,
                A, A + PL_A, Pout, Pout + PL_P, Lh, 128L*Lh);
        L = Lh;
    }

    // MHA
    launch_conv<1,1,64,2>(dim3(1,6,64), WF+WF_MHAIN, A, A + PL_A, nullptr, mib, nullptr,
                          QKV, nullptr, nullptr, nullptr, nullptr,
                          256, 768, 64, 64, 0, 0, 128L*64);
    attn_kernel<<<512, 128>>>(QKV, ATT, ATT + PL_ATT);
    launch_conv<1,1,64,2>(dim3(1,2,64), WF+WF_MHAOUT, ATT, ATT + PL_ATT, nullptr, mob, nullptr,
                          HM, nullptr, nullptr, nullptr, nullptr,
                          256, 256, 64, 64, 0, 0, 128L*64);
    max_t_kernel<<<64, 256>>>(HM, XM);

    // FLUT path (float scratch overlays Bf buffer)
    conv_gemm<15,2,1><<<dim3(32,1,64), 256>>>(WT+O_FLUT, x + 4096, BN+5632, BN+5696, (float*)Bf,
                                              1, 64, 4096, 2048, 7, 1, 12L*4096);
    group_max_kernel<<<64*64, 64>>>((const float*)Bf, FV, 32);
    dense_kernel<<<512, 256>>>(FV, wflut2, nullptr, F2, 4096, 64, 1);

    // PVC path
    conv_gemm<9,2,1><<<dim3(32,1,64), 256>>>(WT+O_PVC, x + 4096, BN+5760, BN+5824, (float*)Bf,
                                             1, 64, 4096, 2048, 4, 1, 12L*4096);
    group_max_kernel<<<64*64, 32>>>((const float*)Bf, PV, 64);
    dense_kernel<<<256, 256>>>(PV, wpvc2, nullptr, P2, 2048, 32, 1);

    // FFT + freq dense
    fft_freq_kernel<<<64, 256>>>(x, freqw, freqb, FQ);

    // concat + FC + sigmoid
    final_kernel<<<64, 128>>>(XM, l, FQ, F2, P2, fcw, fcb, (float*)d_out);
}

// round 15
// speedup vs baseline: 1.0517x; 1.0517x over previous
#include <cuda_runtime.h>
#include <cuda_bf16.h>
#include <math.h>

#define NEG 0.01f
typedef unsigned long long ull;

// ---------------- packed f32x2 helpers (scalar conv path) ----------------
__device__ __forceinline__ ull pk2(float lo, float hi) {
    ull r; asm("mov.b64 %0,{%1,%2};" : "=l"(r) : "f"(lo), "f"(hi)); return r;
}
__device__ __forceinline__ void upk2(ull v, float& lo, float& hi) {
    asm("mov.b64 {%0,%1},%2;" : "=f"(lo), "=f"(hi) : "l"(v));
}
__device__ __forceinline__ ull ffma2(ull a, ull b, ull c) {
    ull d; asm("fma.rn.f32x2 %0,%1,%2,%3;" : "=l"(d) : "l"(a), "l"(b), "l"(c)); return d;
}

// ---------------- bf16 hi/lo split ----------------
__device__ __forceinline__ void split_bf16(float v, unsigned& h, unsigned& l) {
    __nv_bfloat16 hb = __float2bfloat16(v);
    float r = v - __bfloat162float(hb);
    __nv_bfloat16 lb = __float2bfloat16(r);
    h = (unsigned)__bfloat16_as_ushort(hb);
    l = (unsigned)__bfloat16_as_ushort(lb);
}

__device__ __forceinline__ void mma16816(float* c, unsigned a0, unsigned a1, unsigned a2, unsigned a3,
                                         unsigned b0, unsigned b1) {
    asm volatile("mma.sync.aligned.m16n8k16.row.col.f32.bf16.bf16.f32 "
        "{%0,%1,%2,%3}, {%4,%5,%6,%7}, {%8,%9}, {%0,%1,%2,%3};"
        : "+f"(c[0]), "+f"(c[1]), "+f"(c[2]), "+f"(c[3])
        : "r"(a0), "r"(a1), "r"(a2), "r"(a3), "r"(b0), "r"(b1));
}

// ---------------- scratch ----------------
__device__ unsigned g_bufA[64L*256*2048];   // A: hi @0, lo @PL_A
__device__ unsigned g_bufB[64L*256*1024];   // Bf planes / float flut-pvc scratch
__device__ unsigned g_bufP[64L*256*1024];   // P planes ping
__device__ float    g_bufC[64L*256*1024];   // conv0 packed input / rid float out / P pong
__device__ float    g_qkv [64L*768*64];
__device__ unsigned g_att [64L*256*64];     // ATT planes
__device__ float    g_hm  [64L*256*64];
__device__ float g_xmain[64*256];
__device__ float g_fvec[64*4096];
__device__ float g_pvec[64*2048];
__device__ float g_f2[64*64];
__device__ float g_p2[64*32];
__device__ float g_freq[64*32];
__device__ float2 g_tw[4096];
__device__ float g_bn[8192];
__device__ float g_wT[4096];             // scalar-path weights (flut/pvc)
__device__ unsigned g_wf[6549504];       // mma fragment weights (hi/lo bf16)

#define PL_A   (64L*128*2048)
#define PL_B   (64L*128*1024)
#define PL_P   (64L*128*1024)
#define PL_ATT (64L*128*64)
#define PL_X   (64L*8*4096)

#define O_FLUT    0L
#define O_PVC     960L

#define WF_RC1    0L
#define WF_RC2    2949120L
#define WF_RID    5898240L
#define WF_MHAIN  6225920L
#define WF_MHAOUT 6422528L
#define WF_CONV0  6488064L

// ---------------- BN folding ----------------
__global__ void prep_kernel(const float* __restrict__ bn0,
                            const float* __restrict__ rbn1,
                            const float* __restrict__ rbn2,
                            const float* __restrict__ fbn, const float* __restrict__ fb,
                            const float* __restrict__ pbn, const float* __restrict__ pb)
{
    int c = threadIdx.x;
    if (c < 256) {
        {
            float g = bn0[c], b = bn0[256+c], m = bn0[512+c], v = bn0[768+c];
            float s = g * rsqrtf(v + 1e-5f);
            g_bn[c] = s; g_bn[256+c] = b - m*s;
        }
        for (int i = 0; i < 5; i++) {
            const float* p1 = rbn1 + i*1024;
            float g = p1[c], b = p1[256+c], m = p1[512+c], v = p1[768+c];
            float s = g * rsqrtf(v + 1e-5f);
            g_bn[512 + i*256 + c] = s; g_bn[1792 + i*256 + c] = b - m*s;
            const float* p2 = rbn2 + i*1024;
            g = p2[c]; b = p2[256+c]; m = p2[512+c]; v = p2[768+c];
            s = g * rsqrtf(v + 1e-5f);
            g_bn[3072 + i*256 + c] = s; g_bn[4352 + i*256 + c] = b - m*s;
        }
    }
    if (c < 64) {
        float g = fbn[c], b = fbn[64+c], m = fbn[128+c], v = fbn[192+c];
        float s = g * rsqrtf(v + 1e-5f);
        g_bn[5632+c] = s; g_bn[5696+c] = (fb[c] - m)*s + b;
        g = pbn[c]; b = pbn[64+c]; m = pbn[128+c]; v = pbn[192+c];
        s = g * rsqrtf(v + 1e-5f);
        g_bn[5760+c] = s; g_bn[5824+c] = (pb[c] - m)*s + b;
    }
}

// ---------------- pack x for conv0: pair planes, 12->16 padded channels ----------------
__global__ void pack_x_kernel(const float* __restrict__ x,
                              unsigned* __restrict__ xhi, unsigned* __restrict__ xlo)
{
    long i = (long)blockIdx.x*256 + threadIdx.x;
    if (i >= 64L*8*4096) return;
    int t = (int)(i & 4095);
    long r = i >> 12;
    int p = (int)(r & 7);
    int b = (int)(r >> 3);
    int c0 = 2*p, c1 = 2*p + 1;
    float v0 = (c0 < 12) ? x[((long)b*12 + c0)*4096 + t] : 0.f;
    float v1 = (c1 < 12) ? x[((long)b*12 + c1)*4096 + t] : 0.f;
    unsigned h0, l0, h1, l1;
    split_bf16(v0, h0, l0);
    split_bf16(v1, h1, l1);
    xhi[i] = h0 | (h1 << 16);
    xlo[i] = l0 | (l1 << 16);
}

// ---------------- weight transpose (scalar conv path) ----------------
__global__ void wtrans_kernel(const float* __restrict__ src, float* __restrict__ dst,
                              int CI, int KW, long total)
{
    long i = (long)blockIdx.x*256 + threadIdx.x;
    if (i >= total) return;
    int co64 = (int)(i & 63);
    long r = i >> 6;
    int k = (int)(r % KW); r /= KW;
    int ci = (int)(r % CI);
    long ct = r / CI;
    long co = ct*64 + co64;
    dst[i] = src[(co*CI + ci)*KW + k];
}

// ---------------- weight -> mma fragment (hi/lo bf16), CIsrc-padded ----------------
__global__ void wfrag_kernel(const float* __restrict__ src, unsigned* __restrict__ dst,
                             int CIsrc, int KW, int NCH, long total)
{
    long i = (long)blockIdx.x*256 + threadIdx.x;
    if (i >= total) return;
    int r    = (int)(i & 3);
    int lane = (int)((i >> 2) & 31);
    long rest = i >> 7;
    int k  = (int)(rest % KW); rest /= KW;
    int ch = (int)(rest % NCH);
    long ct = rest / NCH;
    int row = lane >> 2;
    int col = (lane & 3) * 2;
    if (r & 1) row += 8;
    if (r >= 2) col += 8;
    long co = ct*16 + row;
    int ci = ch*16 + col;
    float w0 = (ci     < CIsrc) ? src[(co*CIsrc + ci    )*KW + k] : 0.f;
    float w1 = (ci + 1 < CIsrc) ? src[(co*CIsrc + ci + 1)*KW + k] : 0.f;
    unsigned h0, l0, h1, l1;
    split_bf16(w0, h0, l0);
    split_bf16(w1, h1, l1);
    long base = (((ct*NCH + ch)*KW + k)*32 + lane)*8;
    dst[base + r]     = h0 | (h1 << 16);
    dst[base + 4 + r] = l0 | (l1 << 16);
}

// ---------------- tensor-core conv1d (bf16 split planes, fp32 acc) ----------------
template<int KW, int STRIDE, int TT, int CB2>
__global__ void __launch_bounds__(256, 2) conv_mma(
    const unsigned* __restrict__ wf,
    const unsigned* __restrict__ inHi, const unsigned* __restrict__ inLo,
    const float* __restrict__ scale, const float* __restrict__ bias,
    const float* __restrict__ addb,
    float* __restrict__ outF,
    unsigned* __restrict__ outHi, unsigned* __restrict__ outLo,
    unsigned* __restrict__ poolHi, unsigned* __restrict__ poolLo,
    int CI, int CO, int Lin, int Lout, int pad, int dorelu, long inBS)
{
    constexpr int WIN = TT*STRIDE + KW - 1;
    constexpr int NN  = TT / 16;
    constexpr int W   = CB2*10;
    __shared__ __align__(16) unsigned sHi[2][WIN][W];
    __shared__ __align__(16) unsigned sLo[2][WIN][W];

    const int tid  = threadIdx.x;
    const int lane = tid & 31;
    const int wid  = tid >> 5;
    const int wco  = wid & 3;
    const int wt   = wid >> 2;
    const int t0   = blockIdx.x * TT;
    const int co0  = blockIdx.y * 128;
    const int b    = blockIdx.z;
    const int NCH  = CI >> 4;
    const int nst  = NCH / CB2;
    const long ct0 = (co0 >> 4) + wco*2;
    const unsigned* inHib = inHi + (long)b * inBS;
    const unsigned* inLob = inLo + (long)b * inBS;

    float acc[2][NN][4] = {};

    auto stage = [&](int buf, int grp) {
        int cp0 = grp * CB2 * 8;
        for (int idx = tid; idx < CB2*8*WIN; idx += 256) {
            int c2 = idx / (8*WIN);
            int rem = idx - c2*8*WIN;
            int pr = rem / WIN, pos = rem - pr*WIN;
            int j = c2*10 + ((pr < 4) ? (2*pr) : (2*(pr-4)+1));
            int g = t0*STRIDE - pad + pos;
            unsigned vh = 0, vl = 0;
            if (g >= 0 && g < Lin) {
                long gi = (long)(cp0 + c2*8 + pr)*Lin + g;
                vh = __ldg(&inHib[gi]);
                vl = __ldg(&inLob[gi]);
            }
            sHi[buf][pos][j] = vh;
            sLo[buf][pos][j] = vl;
        }
    };

    stage(0, 0);
    __syncthreads();
    for (int s = 0; s < nst; s++) {
        int cur = s & 1;
        if (s + 1 < nst) stage(cur ^ 1, s + 1);
        #pragma unroll
        for (int c2 = 0; c2 < CB2; c2++) {
            int ch = s*CB2 + c2;
            #pragma unroll
            for (int k = 0; k < KW; k++) {
                const uint4* af0 = (const uint4*)(wf + (((ct0*NCH + ch)*KW + k) << 8) + (lane << 3));
                const uint4* af1 = (const uint4*)(wf + ((((ct0+1)*NCH + ch)*KW + k) << 8) + (lane << 3));
                uint4 ahi0 = af0[0], alo0 = af0[1];
                uint4 ahi1 = af1[0], alo1 = af1[1];
                #pragma unroll
                for (int n = 0; n < NN; n++) {
                    int tl = wt*(TT/2) + n*8 + (lane >> 2);
                    int pos = tl*STRIDE + k;
                    int j2 = c2*10 + (lane & 3)*2;
                    uint2 bh = *(const uint2*)&sHi[cur][pos][j2];
                    uint2 bl = *(const uint2*)&sLo[cur][pos][j2];
                    mma16816(acc[0][n], ahi0.x, ahi0.y, ahi0.z, ahi0.w, bh.x, bh.y);
                    mma16816(acc[0][n], alo0.x, alo0.y, alo0.z, alo0.w, bh.x, bh.y);
                    mma16816(acc[0][n], ahi0.x, ahi0.y, ahi0.z, ahi0.w, bl.x, bl.y);
                    mma16816(acc[1][n], ahi1.x, ahi1.y, ahi1.z, ahi1.w, bh.x, bh.y);
                    mma16816(acc[1][n], alo1.x, alo1.y, alo1.z, alo1.w, bh.x, bh.y);
                    mma16816(acc[1][n], ahi1.x, ahi1.y, ahi1.z, ahi1.w, bl.x, bl.y);
                }
            }
        }
        __syncthreads();
    }

    #pragma unroll
    for (int q = 0; q < 2; q++) {
        #pragma unroll
        for (int n = 0; n < NN; n++) {
            int t = t0 + wt*(TT/2) + n*8 + (lane & 3)*2;
            #pragma unroll
            for (int h = 0; h < 2; h++) {
                int co = co0 + wco*32 + q*16 + (lane >> 2) + h*8;
                float sc = scale ? scale[co] : 1.f;
                float bb = bias  ? bias[co]  : 0.f;
                float x0 = acc[q][n][2*h]   * sc + bb;
                float x1 = acc[q][n][2*h+1] * sc + bb;
                if (dorelu) {
                    x0 = x0 >= 0.f ? x0 : NEG*x0;
                    x1 = x1 >= 0.f ? x1 : NEG*x1;
                }
                if (addb) {
                    long obase = ((long)b*CO + co) * Lout + t;
                    float2 a = *(const float2*)&addb[obase];
                    x0 += a.x; x1 += a.y;
                }
                if (outF) {
                    long obase = ((long)b*CO + co) * Lout + t;
                    *(float2*)&outF[obase] = make_float2(x0, x1);
                }
                if (outHi) {
                    float p0 = __shfl_xor_sync(0xffffffffu, x0, 4);
                    float p1 = __shfl_xor_sync(0xffffffffu, x1, 4);
                    if (!(lane & 4)) {
                        unsigned a0h, a0l, b0h, b0l, a1h, a1l, b1h, b1l;
                        split_bf16(x0, a0h, a0l); split_bf16(p0, b0h, b0l);
                        split_bf16(x1, a1h, a1l); split_bf16(p1, b1h, b1l);
                        long pb = ((long)b*(CO >> 1) + (co >> 1))*Lout + t;
                        *(uint2*)&outHi[pb] = make_uint2(a0h | (b0h << 16), a1h | (b1h << 16));
                        *(uint2*)&outLo[pb] = make_uint2(a0l | (b0l << 16), a1l | (b1l << 16));
                    }
                }
                if (poolHi) {
                    float avg = 0.5f*(x0 + x1);
                    float pav = __shfl_xor_sync(0xffffffffu, avg, 4);
                    if (!(lane & 4)) {
                        unsigned ah, al, ph, pl;
                        split_bf16(avg, ah, al); split_bf16(pav, ph, pl);
                        long pb = ((long)b*(CO >> 1) + (co >> 1))*(Lout >> 1) + (t >> 1);
                        poolHi[pb] = ah | (ph << 16);
                        poolLo[pb] = al | (pl << 16);
                    }
                }
            }
        }
    }
}

template<int KW, int STRIDE, int TT, int CB2>
static void launch_conv(dim3 grid,
    const unsigned* wf, const unsigned* inHi, const unsigned* inLo,
    const float* scale, const float* bias, const float* addb,
    float* outF, unsigned* outHi, unsigned* outLo, unsigned* poolHi, unsigned* poolLo,
    int CI, int CO, int Lin, int Lout, int pad, int dorelu, long inBS)
{
    conv_mma<KW,STRIDE,TT,CB2><<<grid, 256>>>(wf, inHi, inLo, scale, bias, addb,
        outF, outHi, outLo, poolHi, poolLo, CI, CO, Lin, Lout, pad, dorelu, inBS);
}

// ---------------- fused rc2 (KW=9,s=1) + rid (KW=1): out = relu(bn(conv9(B))) + conv1(P) ----------------
template<int TT, int CB2>
__global__ void __launch_bounds__(256, 2) conv_mma_fused(
    const unsigned* __restrict__ wf9, const unsigned* __restrict__ wf1,
    const unsigned* __restrict__ bHi, const unsigned* __restrict__ bLo,
    const unsigned* __restrict__ pHi, const unsigned* __restrict__ pLo,
    const float* __restrict__ scale, const float* __restrict__ bias,
    unsigned* __restrict__ outHi, unsigned* __restrict__ outLo,
    unsigned* __restrict__ poolHi, unsigned* __restrict__ poolLo,
    int Lh, long inBS)
{
    constexpr int WIN = TT + 8;
    constexpr int NN  = TT / 16;
    constexpr int W   = CB2*10;
    __shared__ __align__(16) unsigned sBH[2][WIN][W], sBL[2][WIN][W];
    __shared__ __align__(16) unsigned sPH[2][TT][W],  sPL[2][TT][W];

    const int tid  = threadIdx.x;
    const int lane = tid & 31;
    const int wid  = tid >> 5;
    const int wco  = wid & 3;
    const int wt   = wid >> 2;
    const int t0   = blockIdx.x * TT;
    const int co0  = blockIdx.y * 128;
    const int b    = blockIdx.z;
    const int NCH  = 16;
    const int nst  = NCH / CB2;
    const long ct0 = (co0 >> 4) + wco*2;
    const unsigned* bHib = bHi + (long)b * inBS;
    const unsigned* bLob = bLo + (long)b * inBS;
    const unsigned* pHib = pHi + (long)b * inBS;
    const unsigned* pLob = pLo + (long)b * inBS;

    float acc9[2][NN][4] = {};
    float acc1[2][NN][4] = {};

    auto stage = [&](int buf, int grp) {
        int cp0 = grp * CB2 * 8;
        for (int idx = tid; idx < CB2*8*WIN; idx += 256) {
            int c2 = idx / (8*WIN);
            int rem = idx - c2*8*WIN;
            int pr = rem / WIN, pos = rem - pr*WIN;
            int j = c2*10 + ((pr < 4) ? (2*pr) : (2*(pr-4)+1));
            long row = (long)(cp0 + c2*8 + pr)*Lh;
            int g = t0 - 4 + pos;
            unsigned vh = 0, vl = 0;
            if (g >= 0 && g < Lh) {
                vh = __ldg(&bHib[row + g]);
                vl = __ldg(&bLob[row + g]);
            }
            sBH[buf][pos][j] = vh;
            sBL[buf][pos][j] = vl;
            if (pos < TT) {
                sPH[buf][pos][j] = __ldg(&pHib[row + t0 + pos]);
                sPL[buf][pos][j] = __ldg(&pLob[row + t0 + pos]);
            }
        }
    };

    stage(0, 0);
    __syncthreads();
    for (int s = 0; s < nst; s++) {
        int cur = s & 1;
        if (s + 1 < nst) stage(cur ^ 1, s + 1);
        #pragma unroll
        for (int c2 = 0; c2 < CB2; c2++) {
            int ch = s*CB2 + c2;
            #pragma unroll
            for (int k = 0; k < 9; k++) {
                const uint4* af0 = (const uint4*)(wf9 + (((ct0*NCH + ch)*9 + k) << 8) + (lane << 3));
                const uint4* af1 = (const uint4*)(wf9 + ((((ct0+1)*NCH + ch)*9 + k) << 8) + (lane << 3));
                uint4 ahi0 = af0[0], alo0 = af0[1];
                uint4 ahi1 = af1[0], alo1 = af1[1];
                #pragma unroll
                for (int n = 0; n < NN; n++) {
                    int tl = wt*(TT/2) + n*8 + (lane >> 2);
                    int pos = tl + k;
                    int j2 = c2*10 + (lane & 3)*2;
                    uint2 bh = *(const uint2*)&sBH[cur][pos][j2];
                    uint2 bl = *(const uint2*)&sBL[cur][pos][j2];
                    mma16816(acc9[0][n], ahi0.x, ahi0.y, ahi0.z, ahi0.w, bh.x, bh.y);
                    mma16816(acc9[0][n], alo0.x, alo0.y, alo0.z, alo0.w, bh.x, bh.y);
                    mma16816(acc9[0][n], ahi0.x, ahi0.y, ahi0.z, ahi0.w, bl.x, bl.y);
                    mma16816(acc9[1][n], ahi1.x, ahi1.y, ahi1.z, ahi1.w, bh.x, bh.y);
                    mma16816(acc9[1][n], alo1.x, alo1.y, alo1.z, alo1.w, bh.x, bh.y);
                    mma16816(acc9[1][n], ahi1.x, ahi1.y, ahi1.z, ahi1.w, bl.x, bl.y);
                }
            }
            {
                const uint4* af0 = (const uint4*)(wf1 + (((ct0*NCH + ch)) << 8) + (lane << 3));
                const uint4* af1 = (const uint4*)(wf1 + ((((ct0+1)*NCH + ch)) << 8) + (lane << 3));
                uint4 ahi0 = af0[0], alo0 = af0[1];
                uint4 ahi1 = af1[0], alo1 = af1[1];
                #pragma unroll
                for (int n = 0; n < NN; n++) {
                    int pos = wt*(TT/2) + n*8 + (lane >> 2);
                    int j2 = c2*10 + (lane & 3)*2;
                    uint2 bh = *(const uint2*)&sPH[cur][pos][j2];
                    uint2 bl = *(const uint2*)&sPL[cur][pos][j2];
                    mma16816(acc1[0][n], ahi0.x, ahi0.y, ahi0.z, ahi0.w, bh.x, bh.y);
                    mma16816(acc1[0][n], alo0.x, alo0.y, alo0.z, alo0.w, bh.x, bh.y);
                    mma16816(acc1[0][n], ahi0.x, ahi0.y, ahi0.z, ahi0.w, bl.x, bl.y);
                    mma16816(acc1[1][n], ahi1.x, ahi1.y, ahi1.z, ahi1.w, bh.x, bh.y);
                    mma16816(acc1[1][n], alo1.x, alo1.y, alo1.z, alo1.w, bh.x, bh.y);
                    mma16816(acc1[1][n], ahi1.x, ahi1.y, ahi1.z, ahi1.w, bl.x, bl.y);
                }
            }
        }
        __syncthreads();
    }

    #pragma unroll
    for (int q = 0; q < 2; q++) {
        #pragma unroll
        for (int n = 0; n < NN; n++) {
            int t = t0 + wt*(TT/2) + n*8 + (lane & 3)*2;
            #pragma unroll
            for (int h = 0; h < 2; h++) {
                int co = co0 + wco*32 + q*16 + (lane >> 2) + h*8;
                float sc = scale[co];
                float bb = bias[co];
                float x0 = acc9[q][n][2*h]   * sc + bb;
                float x1 = acc9[q][n][2*h+1] * sc + bb;
                x0 = x0 >= 0.f ? x0 : NEG*x0;
                x1 = x1 >= 0.f ? x1 : NEG*x1;
                x0 += acc1[q][n][2*h];
                x1 += acc1[q][n][2*h+1];
                float p0 = __shfl_xor_sync(0xffffffffu, x0, 4);
                float p1 = __shfl_xor_sync(0xffffffffu, x1, 4);
                float avg = 0.5f*(x0 + x1);
                float pav = __shfl_xor_sync(0xffffffffu, avg, 4);
                if (!(lane & 4)) {
                    unsigned a0h, a0l, b0h, b0l, a1h, a1l, b1h, b1l;
                    split_bf16(x0, a0h, a0l); split_bf16(p0, b0h, b0l);
                    split_bf16(x1, a1h, a1l); split_bf16(p1, b1h, b1l);
                    long pb = ((long)b*128 + (co >> 1))*Lh + t;
                    *(uint2*)&outHi[pb] = make_uint2(a0h | (b0h << 16), a1h | (b1h << 16));
                    *(uint2*)&outLo[pb] = make_uint2(a0l | (b0l << 16), a1l | (b1l << 16));
                    unsigned ah, al, ph, pl;
                    split_bf16(avg, ah, al); split_bf16(pav, ph, pl);
                    long qb = ((long)b*128 + (co >> 1))*(Lh >> 1) + (t >> 1);
                    poolHi[qb] = ah | (ph << 16);
                    poolLo[qb] = al | (pl << 16);
                }
            }
        }
    }
}

// ---------------- scalar implicit-GEMM conv1d (CI=1 layers) ----------------
template<int KW, int STRIDE, int CB>
__global__ void __launch_bounds__(256, 2) conv_gemm(
    const float* __restrict__ wT, const float* __restrict__ in,
    const float* __restrict__ scale, const float* __restrict__ bias,
    float* __restrict__ out,
    int CI, int CO, int Lin, int Lout, int pad, int dorelu, long inBS)
{
    constexpr int WIN  = 64*STRIDE + KW - 1;
    constexpr int WINP = (WIN + 11) & ~3;
    constexpr int RW   = 3*STRIDE + KW;
    constexpr int NV   = (RW + 3) / 4;
    __shared__ __align__(16) float sW[2][CB*KW*64];
    __shared__ __align__(16) float sIn[2][CB][WINP];

    const int tid = threadIdx.x;
    const int tx = tid & 15, ty = tid >> 4;
    const int t0 = blockIdx.x * 64, co0 = blockIdx.y * 64;
    const int b  = blockIdx.z;
    const float* inb = in + (long)b * inBS;
    const long wstride = (long)KW * 64;
    const float* wbase = wT + (long)blockIdx.y * CI * wstride;

    ull acc01[4], acc23[4];
    #pragma unroll
    for (int j = 0; j < 4; j++) { acc01[j] = 0ull; acc23[j] = 0ull; }

    const int nst = CI / CB;
    auto stage = [&](int buf, int cib) {
        const float4* ws = (const float4*)(wbase + (long)cib * wstride);
        float4* wd = (float4*)sW[buf];
        for (int idx = tid; idx < CB*KW*16; idx += 256) wd[idx] = ws[idx];
        for (int idx = tid; idx < CB*WIN; idx += 256) {
            int c = idx / WIN, w = idx - c*WIN;
            int g = t0*STRIDE - pad + w;
            sIn[buf][c][w] = (g >= 0 && g < Lin) ? __ldg(&inb[(long)(cib+c)*Lin + g]) : 0.f;
        }
    };

    stage(0, 0);
    __syncthreads();
    for (int s = 0; s < nst; s++) {
        int cur = s & 1;
        if (s + 1 < nst) stage(cur ^ 1, (s + 1) * CB);
        #pragma unroll
        for (int c = 0; c < CB; c++) {
            float4 wv4[NV];
            const float4* ip = (const float4*)&sIn[cur][c][tx*4*STRIDE];
            #pragma unroll
            for (int v = 0; v < NV; v++) wv4[v] = ip[v];
            const float* wfp = (const float*)wv4;
            ull bc[RW];
            #pragma unroll
            for (int m = 0; m < RW; m++) bc[m] = pk2(wfp[m], wfp[m]);
            const float* wrow = sW[cur] + c*KW*64 + ty*4;
            #pragma unroll
            for (int k = 0; k < KW; k++) {
                ulonglong2 wv = *(const ulonglong2*)(wrow + k*64);
                #pragma unroll
                for (int j = 0; j < 4; j++) {
                    acc01[j] = ffma2(wv.x, bc[j*STRIDE + k], acc01[j]);
                    acc23[j] = ffma2(wv.y, bc[j*STRIDE + k], acc23[j]);
                }
            }
        }
        __syncthreads();
    }

    float r[4][4];
    #pragma unroll
    for (int j = 0; j < 4; j++) { upk2(acc01[j], r[0][j], r[1][j]); upk2(acc23[j], r[2][j], r[3][j]); }
    #pragma unroll
    for (int i = 0; i < 4; i++) {
        int co = co0 + ty*4 + i;
        float sc = scale ? scale[co] : 1.f;
        float bb = bias  ? bias[co]  : 0.f;
        long obase = ((long)b*CO + co) * Lout + t0 + tx*4;
        float4 v;
        v.x = r[i][0]*sc + bb; v.y = r[i][1]*sc + bb;
        v.z = r[i][2]*sc + bb; v.w = r[i][3]*sc + bb;
        if (dorelu) {
            v.x = v.x >= 0.f ? v.x : NEG*v.x; v.y = v.y >= 0.f ? v.y : NEG*v.y;
            v.z = v.z >= 0.f ? v.z : NEG*v.z; v.w = v.w >= 0.f ? v.w : NEG*v.w;
        }
        *(float4*)&out[obase] = v;
    }
}

// ---------------- attention per (batch, head): writes ATT pair planes ----------------
__global__ void __launch_bounds__(128) attn_kernel(const float* __restrict__ qkv,
                                                   unsigned* __restrict__ ohi,
                                                   unsigned* __restrict__ olo)
{
    __shared__ float q[32][64], kk[32][64], vv[32][64];
    __shared__ float att[64][65];
    int bh = blockIdx.x; int b = bh >> 3, h = bh & 7;
    const float* base = qkv + (long)b*768*64 + (long)h*32*64;
    int tid = threadIdx.x;
    for (int idx = tid; idx < 2048; idx += 128) {
        int d = idx >> 6, s = idx & 63;
        q [d][s] = base[d*64 + s];
        kk[d][s] = base[256*64 + d*64 + s];
        vv[d][s] = base[512*64 + d*64 + s];
    }
    __syncthreads();
    for (int e = tid; e < 4096; e += 128) {
        int qs = e >> 6, ks = e & 63;
        float s = 0.f;
        #pragma unroll
        for (int d = 0; d < 32; d++) s = fmaf(q[d][qs], kk[d][ks], s);
        att[qs][ks] = s * 0.17677669529663687f;
    }
    __syncthreads();
    if (tid < 64) {
        float m = -1e30f;
        for (int ks = 0; ks < 64; ks++) m = fmaxf(m, att[tid][ks]);
        float sum = 0.f;
        for (int ks = 0; ks < 64; ks++) { float e = expf(att[tid][ks] - m); att[tid][ks] = e; sum += e; }
        float inv = 1.f / sum;
        for (int ks = 0; ks < 64; ks++) att[tid][ks] *= inv;
    }
    __syncthreads();
    for (int e = tid; e < 1024; e += 128) {
        int m = e >> 6, qs = e & 63;
        float s0 = 0.f, s1 = 0.f;
        #pragma unroll
        for (int ks = 0; ks < 64; ks++) {
            float a = att[qs][ks];
            s0 = fmaf(a, vv[2*m][ks],   s0);
            s1 = fmaf(a, vv[2*m+1][ks], s1);
        }
        unsigned h0, l0, h1, l1;
        split_bf16(s0, h0, l0);
        split_bf16(s1, h1, l1);
        long idx = ((long)b*128 + h*16 + m)*64 + qs;
        ohi[idx] = h0 | (h1 << 16);
        olo[idx] = l0 | (l1 << 16);
    }
}

__global__ void max_t_kernel(const float* __restrict__ in, float* __restrict__ out)
{
    int b = blockIdx.x, c = threadIdx.x;
    const float* r = in + ((long)b*256 + c) * 64;
    float m = r[0];
    #pragma unroll
    for (int t = 1; t < 64; t++) m = fmaxf(m, r[t]);
    out[b*256 + c] = m;
}

__global__ void group_max_kernel(const float* __restrict__ in, float* __restrict__ out, int GS)
{
    int row = blockIdx.x; int g = threadIdx.x; int G = blockDim.x;
    const float* r = in + (long)row*G*GS + (long)g*GS;
    float m = r[0];
    for (int j = 1; j < GS; j++) m = fmaxf(m, r[j]);
    out[(long)row*G + g] = m;
}

// ---------------- dense: one warp per (batch, output) ----------------
__global__ void __launch_bounds__(256) dense_kernel(const float* __restrict__ in,
                                                    const float* __restrict__ w,
                                                    const float* __restrict__ bias,
                                                    float* __restrict__ out,
                                                    int IN, int OUT, int dorelu)
{
    int wid = threadIdx.x >> 5, lane = threadIdx.x & 31;
    int gid = blockIdx.x*8 + wid;
    int b = gid / OUT, o = gid - b*OUT;
    if (b >= 64) return;
    const float* iv = in + (long)b*IN;
    const float* wr = w + (long)o*IN;
    float s = 0.f;
    for (int i = lane; i < IN; i += 32) s = fmaf(iv[i], wr[i], s);
    #pragma unroll
    for (int off = 16; off > 0; off >>= 1) s += __shfl_down_sync(0xffffffffu, s, off);
    if (lane == 0) {
        if (bias) s += bias[o];
        if (dorelu) s = (s >= 0.f) ? s : NEG*s;
        out[b*OUT + o] = s;
    }
}

__global__ void twiddle_kernel()
{
    int i = blockIdx.x*256 + threadIdx.x;
    if (i < 4096) {
        double a = -2.0 * 3.14159265358979323846 * (double)i / 4096.0;
        g_tw[i] = make_float2((float)cos(a), (float)sin(a));
    }
}

__global__ void __launch_bounds__(256) fft_freq_kernel(const float* __restrict__ x,
                                                       const float* __restrict__ fw,
                                                       const float* __restrict__ fb,
                                                       float* __restrict__ out)
{
    __shared__ float2 stw[4096];
    __shared__ float smag[256];
    __shared__ float sred[256];
    int b = blockIdx.x, tid = threadIdx.x;
    for (int i = tid; i < 4096; i += 256) stw[i] = g_tw[i];
    const float* xr = x + ((long)b*12 + 1) * 4096;
    __syncthreads();
    int k = 50 + tid;
    float re0 = 0.f, im0 = 0.f, re1 = 0.f, im1 = 0.f;
    for (int n = 0; n < 4096; n += 4) {
        float4 xv = *(const float4*)&xr[n];
        int i0 = (k*n) & 4095;
        int i1 = (i0 + k) & 4095;
        int i2 = (i0 + 2*k) & 4095;
        int i3 = (i0 + 3*k) & 4095;
        float2 c0 = stw[i0], c1 = stw[i1], c2 = stw[i2], c3 = stw[i3];
        re0 = fmaf(xv.x, c0.x, re0); im0 = fmaf(xv.x, c0.y, im0);
        re1 = fmaf(xv.y, c1.x, re1); im1 = fmaf(xv.y, c1.y, im1);
        re0 = fmaf(xv.z, c2.x, re0); im0 = fmaf(xv.z, c2.y, im0);
        re1 = fmaf(xv.w, c3.x, re1); im1 = fmaf(xv.w, c3.y, im1);
    }
    float re = re0 + re1, im = im0 + im1;
    float mag = sqrtf(re*re + im*im);
    smag[tid] = mag; sred[tid] = mag;
    __syncthreads();
    for (int s = 128; s > 0; s >>= 1) {
        if (tid < s) sred[tid] = fmaxf(sred[tid], sred[tid+s]);
        __syncthreads();
    }
    float mx = sred[0];
    smag[tid] = (mx > 0.f) ? mag/mx : mag;
    __syncthreads();
    if (tid < 32) {
        float s = fb[tid];
        const float* wr = fw + tid*256;
        for (int j = 0; j < 256; j++) s = fmaf(smag[j], wr[j], s);
        out[b*32 + tid] = (s >= 0.f) ? s : NEG*s;
    }
}

__global__ void final_kernel(const float* __restrict__ xm, const float* __restrict__ l,
                             const float* __restrict__ fq, const float* __restrict__ f2,
                             const float* __restrict__ p2, const float* __restrict__ fcw,
                             const float* __restrict__ fcb, float* __restrict__ out)
{
    __shared__ float comb[396];
    int b = blockIdx.x, tid = threadIdx.x;
    for (int i = tid; i < 256; i += 128) comb[i] = xm[b*256 + i];
    if (tid < 12) comb[256 + tid] = l[b*12 + tid];
    if (tid < 32) comb[268 + tid] = fq[b*32 + tid];
    if (tid < 64) comb[300 + tid] = f2[b*64 + tid];
    if (tid < 32) comb[364 + tid] = p2[b*32 + tid];
    __syncthreads();
    if (tid < 27) {
        float s = fcb[tid];
        const float* wr = fcw + tid*396;
        for (int j = 0; j < 396; j++) s = fmaf(comb[j], wr[j], s);
        out[b*27 + tid] = s;
        out[64*27 + b*27 + tid] = 1.f / (1.f + expf(-s));
    }
}

// ---------------- host launch ----------------
extern "C" void kernel_launch(void* const* d_in, const int* in_sizes, int n_in,
                              void* d_out, int out_size)
{
    (void)in_sizes; (void)n_in; (void)out_size;
    const float* x      = (const float*)d_in[0];
    const float* l      = (const float*)d_in[1];
    const float* conv_w = (const float*)d_in[2];
    const float* bn0    = (const float*)d_in[3];
    const float* rc1    = (const float*)d_in[4];
    const float* rbn1   = (const float*)d_in[5];
    const float* rc2    = (const float*)d_in[6];
    const float* rbn2   = (const float*)d_in[7];
    const float* rid    = (const float*)d_in[8];
    const float* miw    = (const float*)d_in[9];
    const float* mib    = (const float*)d_in[10];
    const float* mow    = (const float*)d_in[11];
    const float* mob    = (const float*)d_in[12];
    const float* fw     = (const float*)d_in[13];
    const float* fbv    = (const float*)d_in[14];
    const float* fbn    = (const float*)d_in[15];
    const float* pw     = (const float*)d_in[16];
    const float* pbv    = (const float*)d_in[17];
    const float* pbn    = (const float*)d_in[18];
    const float* wflut2 = (const float*)d_in[19];
    const float* wpvc2  = (const float*)d_in[20];
    const float* freqw  = (const float*)d_in[21];
    const float* freqb  = (const float*)d_in[22];
    const float* fcw    = (const float*)d_in[23];
    const float* fcb    = (const float*)d_in[24];

    unsigned *A, *Bf, *P0, *ATT, *WF;
    float *C, *QKV, *HM, *XM, *FV, *PV, *F2, *P2, *FQ, *BN, *WT;
    cudaGetSymbolAddress((void**)&A,   g_bufA);
    cudaGetSymbolAddress((void**)&Bf,  g_bufB);
    cudaGetSymbolAddress((void**)&P0,  g_bufP);
    cudaGetSymbolAddress((void**)&C,   g_bufC);
    cudaGetSymbolAddress((void**)&QKV, g_qkv);
    cudaGetSymbolAddress((void**)&ATT, g_att);
    cudaGetSymbolAddress((void**)&HM,  g_hm);
    cudaGetSymbolAddress((void**)&XM,  g_xmain);
    cudaGetSymbolAddress((void**)&FV,  g_fvec);
    cudaGetSymbolAddress((void**)&PV,  g_pvec);
    cudaGetSymbolAddress((void**)&F2,  g_f2);
    cudaGetSymbolAddress((void**)&P2,  g_p2);
    cudaGetSymbolAddress((void**)&FQ,  g_freq);
    cudaGetSymbolAddress((void**)&BN,  g_bn);
    cudaGetSymbolAddress((void**)&WT,  g_wT);
    cudaGetSymbolAddress((void**)&WF,  g_wf);

    unsigned* XP = (unsigned*)C;   // conv0 packed input planes
    unsigned* P1 = (unsigned*)C;   // P pong (free after last separate-rid layer)

    prep_kernel<<<1, 256>>>(bn0, rbn1, rbn2, fbn, fbv, pbn, pbv);
    twiddle_kernel<<<16, 256>>>();
    pack_x_kernel<<<8192, 256>>>(x, XP, XP + PL_X);

    auto wt = [&](const float* src, long off, int CO, int CI, int KW) {
        long tot = (long)CO*CI*KW;
        wtrans_kernel<<<(unsigned)((tot + 255)/256), 256>>>(src, WT + off, CI, KW, tot);
    };
    wt(fw, O_FLUT, 64, 1, 15);
    wt(pw, O_PVC,  64, 1, 9);

    auto wfp = [&](const float* src, long off, int CO, int CIsrc, int CIpad, int KW) {
        long tot = (long)(CO/16)*(CIpad/16)*KW*128;
        wfrag_kernel<<<(unsigned)((tot + 255)/256), 256>>>(src, WF + off, CIsrc, KW, CIpad/16, tot);
    };
    for (int i = 0; i < 5; i++) {
        wfp(rc1 + (long)i*256*256*9, WF_RC1 + (long)i*589824, 256, 256, 256, 9);
        wfp(rc2 + (long)i*256*256*9, WF_RC2 + (long)i*589824, 256, 256, 256, 9);
        wfp(rid + (long)i*256*256,   WF_RID + (long)i*65536,  256, 256, 256, 1);
    }
    wfp(miw,    WF_MHAIN,  768, 256, 256, 1);
    wfp(mow,    WF_MHAOUT, 256, 256, 256, 1);
    wfp(conv_w, WF_CONV0,  256,  12,  16, 15);

    // conv0: mma path -> A planes + pooled P planes (into P0)
    launch_conv<15,2,64,1>(dim3(32,2,64), WF+WF_CONV0, XP, XP + PL_X, BN+0, BN+256, nullptr,
                           nullptr, A, A + PL_A, P0, P0 + PL_P,
                           16, 256, 4096, 2048, 7, 1, 8L*4096);

    unsigned* Pcur = P0;
    unsigned* Palt = P1;
    int L = 2048;
    for (int i = 0; i < 5; i++) {
        int Lh = L/2;
        if (Lh >= 256) {
            // R11 config: separate rid (rc2 pools into Pcur, which rc2 doesn't read)
            launch_conv<9,2,128,1>(dim3(Lh/128,2,64), WF+WF_RC1 + (long)i*589824, A, A + PL_A,
                BN+512+i*256, BN+1792+i*256, nullptr, nullptr, Bf, Bf + PL_B, nullptr, nullptr,
                256, 256, L, Lh, 4, 1, 128L*L);
            launch_conv<1,1,128,2>(dim3(Lh/128,2,64), WF+WF_RID + (long)i*65536, Pcur, Pcur + PL_P,
                nullptr, nullptr, nullptr, C, nullptr, nullptr, nullptr, nullptr,
                256, 256, Lh, Lh, 0, 0, 128L*Lh);
            launch_conv<9,1,128,2>(dim3(Lh/128,2,64), WF+WF_RC2 + (long)i*589824, Bf, Bf + PL_B,
                BN+3072+i*256, BN+4352+i*256, C, nullptr, A, A + PL_A, Pcur, Pcur + PL_P,
                256, 256, Lh, Lh, 4, 1, 128L*Lh);
        } else {
            // small layers: fused rc2+rid, ping-pong P
            if (Lh == 128)
                launch_conv<9,2,64,1>(dim3(2,2,64), WF+WF_RC1 + (long)i*589824, A, A + PL_A,
                    BN+512+i*256, BN+1792+i*256, nullptr, nullptr, Bf, Bf + PL_B, nullptr, nullptr,
                    256, 256, L, Lh, 4, 1, 128L*L);
            else
                launch_conv<9,2,32,1>(dim3(2,2,64), WF+WF_RC1 + (long)i*589824, A, A + PL_A,
                    BN+512+i*256, BN+1792+i*256, nullptr, nullptr, Bf, Bf + PL_B, nullptr, nullptr,
                    256, 256, L, Lh, 4, 1, 128L*L);
            conv_mma_fused<64,2><<<dim3(Lh/64,2,64), 256>>>(
                WF+WF_RC2 + (long)i*589824, WF+WF_RID + (long)i*65536,
                Bf, Bf + PL_B, Pcur, Pcur + PL_P,
                BN+3072+i*256, BN+4352+i*256,
                A, A + PL_A, Palt, Palt + PL_P, Lh, 128L*Lh);
            unsigned* tmp = Pcur; Pcur = Palt; Palt = tmp;
        }
        L = Lh;
    }

    // MHA
    launch_conv<1,1,64,2>(dim3(1,6,64), WF+WF_MHAIN, A, A + PL_A, nullptr, mib, nullptr,
                          QKV, nullptr, nullptr, nullptr, nullptr,
                          256, 768, 64, 64, 0, 0, 128L*64);
    attn_kernel<<<512, 128>>>(QKV, ATT, ATT + PL_ATT);
    launch_conv<1,1,64,2>(dim3(1,2,64), WF+WF_MHAOUT, ATT, ATT + PL_ATT, nullptr, mob, nullptr,
                          HM, nullptr, nullptr, nullptr, nullptr,
                          256, 256, 64, 64, 0, 0, 128L*64);
    max_t_kernel<<<64, 256>>>(HM, XM);

    // FLUT path (float scratch overlays Bf buffer)
    conv_gemm<15,2,1><<<dim3(32,1,64), 256>>>(WT+O_FLUT, x + 4096, BN+5632, BN+5696, (float*)Bf,
                                              1, 64, 4096, 2048, 7, 1, 12L*4096);
    group_max_kernel<<<64*64, 64>>>((const float*)Bf, FV, 32);
    dense_kernel<<<512, 256>>>(FV, wflut2, nullptr, F2, 4096, 64, 1);

    // PVC path
    conv_gemm<9,2,1><<<dim3(32,1,64), 256>>>(WT+O_PVC, x + 4096, BN+5760, BN+5824, (float*)Bf,
                                             1, 64, 4096, 2048, 4, 1, 12L*4096);
    group_max_kernel<<<64*64, 32>>>((const float*)Bf, PV, 64);
    dense_kernel<<<256, 256>>>(PV, wpvc2, nullptr, P2, 2048, 32, 1);

    // FFT + freq dense
    fft_freq_kernel<<<64, 256>>>(x, freqw, freqb, FQ);

    // concat + FC + sigmoid
    final_kernel<<<64, 128>>>(XM, l, FQ, F2, P2, fcw, fcb, (float*)d_out);
}

// round 16
// speedup vs baseline: 1.1072x; 1.0528x over previous
#include <cuda_runtime.h>
#include <cuda_bf16.h>
#include <math.h>

#define NEG 0.01f
typedef unsigned long long ull;

// ---------------- packed f32x2 helpers (scalar conv path) ----------------
__device__ __forceinline__ ull pk2(float lo, float hi) {
    ull r; asm("mov.b64 %0,{%1,%2};" : "=l"(r) : "f"(lo), "f"(hi)); return r;
}
__device__ __forceinline__ void upk2(ull v, float& lo, float& hi) {
    asm("mov.b64 {%0,%1},%2;" : "=f"(lo), "=f"(hi) : "l"(v));
}
__device__ __forceinline__ ull ffma2(ull a, ull b, ull c) {
    ull d; asm("fma.rn.f32x2 %0,%1,%2,%3;" : "=l"(d) : "l"(a), "l"(b), "l"(c)); return d;
}

// ---------------- bf16 hi/lo split ----------------
__device__ __forceinline__ void split_bf16(float v, unsigned& h, unsigned& l) {
    __nv_bfloat16 hb = __float2bfloat16(v);
    float r = v - __bfloat162float(hb);
    __nv_bfloat16 lb = __float2bfloat16(r);
    h = (unsigned)__bfloat16_as_ushort(hb);
    l = (unsigned)__bfloat16_as_ushort(lb);
}

__device__ __forceinline__ void mma16816(float* c, unsigned a0, unsigned a1, unsigned a2, unsigned a3,
                                         unsigned b0, unsigned b1) {
    asm volatile("mma.sync.aligned.m16n8k16.row.col.f32.bf16.bf16.f32 "
        "{%0,%1,%2,%3}, {%4,%5,%6,%7}, {%8,%9}, {%0,%1,%2,%3};"
        : "+f"(c[0]), "+f"(c[1]), "+f"(c[2]), "+f"(c[3])
        : "r"(a0), "r"(a1), "r"(a2), "r"(a3), "r"(b0), "r"(b1));
}

// ---------------- cp.async helpers ----------------
__device__ __forceinline__ void cp4(unsigned* dst, const unsigned* src, bool pred) {
    unsigned d = (unsigned)__cvta_generic_to_shared(dst);
    asm volatile("cp.async.ca.shared.global [%0], [%1], 4, %2;"
                 :: "r"(d), "l"(src), "r"(pred ? 4 : 0));
}
__device__ __forceinline__ void cp_commit() {
    asm volatile("cp.async.commit_group;");
}
template<int N>
__device__ __forceinline__ void cp_wait() {
    asm volatile("cp.async.wait_group %0;" :: "n"(N));
}

// ---------------- scratch ----------------
__device__ unsigned g_bufA[64L*256*2048];   // A: hi @0, lo @PL_A
__device__ unsigned g_bufB[64L*256*1024];   // Bf planes / float flut-pvc scratch
__device__ unsigned g_bufP[64L*256*1024];   // P planes ping
__device__ float    g_bufC[64L*256*1024];   // conv0 packed input / rid float out / P pong
__device__ float    g_qkv [64L*768*64];
__device__ unsigned g_att [64L*256*64];     // ATT planes
__device__ float    g_hm  [64L*256*64];
__device__ float g_xmain[64*256];
__device__ float g_fvec[64*4096];
__device__ float g_pvec[64*2048];
__device__ float g_f2[64*64];
__device__ float g_p2[64*32];
__device__ float g_freq[64*32];
__device__ float2 g_tw[4096];
__device__ float g_bn[8192];
__device__ float g_wT[4096];             // scalar-path weights (flut/pvc)
__device__ unsigned g_wf[6549504];       // mma fragment weights (hi/lo bf16)

#define PL_A   (64L*128*2048)
#define PL_B   (64L*128*1024)
#define PL_P   (64L*128*1024)
#define PL_ATT (64L*128*64)
#define PL_X   (64L*8*4096)

#define O_FLUT    0L
#define O_PVC     960L

#define WF_RC1    0L
#define WF_RC2    2949120L
#define WF_RID    5898240L
#define WF_MHAIN  6225920L
#define WF_MHAOUT 6422528L
#define WF_CONV0  6488064L

// ---------------- BN folding ----------------
__global__ void prep_kernel(const float* __restrict__ bn0,
                            const float* __restrict__ rbn1,
                            const float* __restrict__ rbn2,
                            const float* __restrict__ fbn, const float* __restrict__ fb,
                            const float* __restrict__ pbn, const float* __restrict__ pb)
{
    int c = threadIdx.x;
    if (c < 256) {
        {
            float g = bn0[c], b = bn0[256+c], m = bn0[512+c], v = bn0[768+c];
            float s = g * rsqrtf(v + 1e-5f);
            g_bn[c] = s; g_bn[256+c] = b - m*s;
        }
        for (int i = 0; i < 5; i++) {
            const float* p1 = rbn1 + i*1024;
            float g = p1[c], b = p1[256+c], m = p1[512+c], v = p1[768+c];
            float s = g * rsqrtf(v + 1e-5f);
            g_bn[512 + i*256 + c] = s; g_bn[1792 + i*256 + c] = b - m*s;
            const float* p2 = rbn2 + i*1024;
            g = p2[c]; b = p2[256+c]; m = p2[512+c]; v = p2[768+c];
            s = g * rsqrtf(v + 1e-5f);
            g_bn[3072 + i*256 + c] = s; g_bn[4352 + i*256 + c] = b - m*s;
        }
    }
    if (c < 64) {
        float g = fbn[c], b = fbn[64+c], m = fbn[128+c], v = fbn[192+c];
        float s = g * rsqrtf(v + 1e-5f);
        g_bn[5632+c] = s; g_bn[5696+c] = (fb[c] - m)*s + b;
        g = pbn[c]; b = pbn[64+c]; m = pbn[128+c]; v = pbn[192+c];
        s = g * rsqrtf(v + 1e-5f);
        g_bn[5760+c] = s; g_bn[5824+c] = (pb[c] - m)*s + b;
    }
}

// ---------------- pack x for conv0: pair planes, 12->16 padded channels ----------------
__global__ void pack_x_kernel(const float* __restrict__ x,
                              unsigned* __restrict__ xhi, unsigned* __restrict__ xlo)
{
    long i = (long)blockIdx.x*256 + threadIdx.x;
    if (i >= 64L*8*4096) return;
    int t = (int)(i & 4095);
    long r = i >> 12;
    int p = (int)(r & 7);
    int b = (int)(r >> 3);
    int c0 = 2*p, c1 = 2*p + 1;
    float v0 = (c0 < 12) ? x[((long)b*12 + c0)*4096 + t] : 0.f;
    float v1 = (c1 < 12) ? x[((long)b*12 + c1)*4096 + t] : 0.f;
    unsigned h0, l0, h1, l1;
    split_bf16(v0, h0, l0);
    split_bf16(v1, h1, l1);
    xhi[i] = h0 | (h1 << 16);
    xlo[i] = l0 | (l1 << 16);
}

// ---------------- weight transpose (scalar conv path) ----------------
__global__ void wtrans_kernel(const float* __restrict__ src, float* __restrict__ dst,
                              int CI, int KW, long total)
{
    long i = (long)blockIdx.x*256 + threadIdx.x;
    if (i >= total) return;
    int co64 = (int)(i & 63);
    long r = i >> 6;
    int k = (int)(r % KW); r /= KW;
    int ci = (int)(r % CI);
    long ct = r / CI;
    long co = ct*64 + co64;
    dst[i] = src[(co*CI + ci)*KW + k];
}

// ---------------- weight -> mma fragment (hi/lo bf16), CIsrc-padded ----------------
__global__ void wfrag_kernel(const float* __restrict__ src, unsigned* __restrict__ dst,
                             int CIsrc, int KW, int NCH, long total)
{
    long i = (long)blockIdx.x*256 + threadIdx.x;
    if (i >= total) return;
    int r    = (int)(i & 3);
    int lane = (int)((i >> 2) & 31);
    long rest = i >> 7;
    int k  = (int)(rest % KW); rest /= KW;
    int ch = (int)(rest % NCH);
    long ct = rest / NCH;
    int row = lane >> 2;
    int col = (lane & 3) * 2;
    if (r & 1) row += 8;
    if (r >= 2) col += 8;
    long co = ct*16 + row;
    int ci = ch*16 + col;
    float w0 = (ci     < CIsrc) ? src[(co*CIsrc + ci    )*KW + k] : 0.f;
    float w1 = (ci + 1 < CIsrc) ? src[(co*CIsrc + ci + 1)*KW + k] : 0.f;
    unsigned h0, l0, h1, l1;
    split_bf16(w0, h0, l0);
    split_bf16(w1, l1, l1);  // placeholder overwritten below
    split_bf16(w1, h1, l1);
    long base = (((ct*NCH + ch)*KW + k)*32 + lane)*8;
    dst[base + r]     = h0 | (h1 << 16);
    dst[base + 4 + r] = l0 | (l1 << 16);
}

// ---------------- tensor-core conv1d (bf16 split planes, fp32 acc, cp.async staging) ----------------
template<int KW, int STRIDE, int TT, int CB2>
__global__ void __launch_bounds__(256, 2) conv_mma(
    const unsigned* __restrict__ wf,
    const unsigned* __restrict__ inHi, const unsigned* __restrict__ inLo,
    const float* __restrict__ scale, const float* __restrict__ bias,
    const float* __restrict__ addb,
    float* __restrict__ outF,
    unsigned* __restrict__ outHi, unsigned* __restrict__ outLo,
    unsigned* __restrict__ poolHi, unsigned* __restrict__ poolLo,
    int CI, int CO, int Lin, int Lout, int pad, int dorelu, long inBS)
{
    constexpr int WIN = TT*STRIDE + KW - 1;
    constexpr int NN  = TT / 16;
    constexpr int W   = CB2*10;
    __shared__ __align__(16) unsigned sHi[2][WIN][W];
    __shared__ __align__(16) unsigned sLo[2][WIN][W];

    const int tid  = threadIdx.x;
    const int lane = tid & 31;
    const int wid  = tid >> 5;
    const int wco  = wid & 3;
    const int wt   = wid >> 2;
    const int t0   = blockIdx.x * TT;
    const int co0  = blockIdx.y * 128;
    const int b    = blockIdx.z;
    const int NCH  = CI >> 4;
    const int nst  = NCH / CB2;
    const long ct0 = (co0 >> 4) + wco*2;
    const unsigned* inHib = inHi + (long)b * inBS;
    const unsigned* inLob = inLo + (long)b * inBS;

    float acc[2][NN][4] = {};

    auto stage = [&](int buf, int grp) {
        int cp0 = grp * CB2 * 8;
        for (int idx = tid; idx < CB2*8*WIN; idx += 256) {
            int c2 = idx / (8*WIN);
            int rem = idx - c2*8*WIN;
            int pr = rem / WIN, pos = rem - pr*WIN;
            int j = c2*10 + ((pr < 4) ? (2*pr) : (2*(pr-4)+1));
            int g = t0*STRIDE - pad + pos;
            bool ok = (g >= 0 && g < Lin);
            long gi = (long)(cp0 + c2*8 + pr)*Lin + (ok ? g : 0);
            cp4(&sHi[buf][pos][j], inHib + gi, ok);
            cp4(&sLo[buf][pos][j], inLob + gi, ok);
        }
        cp_commit();
    };

    stage(0, 0);
    cp_wait<0>();
    __syncthreads();
    for (int s = 0; s < nst; s++) {
        int cur = s & 1;
        if (s + 1 < nst) stage(cur ^ 1, s + 1);
        #pragma unroll
        for (int c2 = 0; c2 < CB2; c2++) {
            int ch = s*CB2 + c2;
            #pragma unroll
            for (int k = 0; k < KW; k++) {
                const uint4* af0 = (const uint4*)(wf + (((ct0*NCH + ch)*KW + k) << 8) + (lane << 3));
                const uint4* af1 = (const uint4*)(wf + ((((ct0+1)*NCH + ch)*KW + k) << 8) + (lane << 3));
                uint4 ahi0 = af0[0], alo0 = af0[1];
                uint4 ahi1 = af1[0], alo1 = af1[1];
                #pragma unroll
                for (int n = 0; n < NN; n++) {
                    int tl = wt*(TT/2) + n*8 + (lane >> 2);
                    int pos = tl*STRIDE + k;
                    int j2 = c2*10 + (lane & 3)*2;
                    uint2 bh = *(const uint2*)&sHi[cur][pos][j2];
                    uint2 bl = *(const uint2*)&sLo[cur][pos][j2];
                    mma16816(acc[0][n], ahi0.x, ahi0.y, ahi0.z, ahi0.w, bh.x, bh.y);
                    mma16816(acc[0][n], alo0.x, alo0.y, alo0.z, alo0.w, bh.x, bh.y);
                    mma16816(acc[0][n], ahi0.x, ahi0.y, ahi0.z, ahi0.w, bl.x, bl.y);
                    mma16816(acc[1][n], ahi1.x, ahi1.y, ahi1.z, ahi1.w, bh.x, bh.y);
                    mma16816(acc[1][n], alo1.x, alo1.y, alo1.z, alo1.w, bh.x, bh.y);
                    mma16816(acc[1][n], ahi1.x, ahi1.y, ahi1.z, ahi1.w, bl.x, bl.y);
                }
            }
        }
        if (s + 1 < nst) cp_wait<0>();
        __syncthreads();
    }

    #pragma unroll
    for (int q = 0; q < 2; q++) {
        #pragma unroll
        for (int n = 0; n < NN; n++) {
            int t = t0 + wt*(TT/2) + n*8 + (lane & 3)*2;
            #pragma unroll
            for (int h = 0; h < 2; h++) {
                int co = co0 + wco*32 + q*16 + (lane >> 2) + h*8;
                float sc = scale ? scale[co] : 1.f;
                float bb = bias  ? bias[co]  : 0.f;
                float x0 = acc[q][n][2*h]   * sc + bb;
                float x1 = acc[q][n][2*h+1] * sc + bb;
                if (dorelu) {
                    x0 = x0 >= 0.f ? x0 : NEG*x0;
                    x1 = x1 >= 0.f ? x1 : NEG*x1;
                }
                if (addb) {
                    long obase = ((long)b*CO + co) * Lout + t;
                    float2 a = *(const float2*)&addb[obase];
                    x0 += a.x; x1 += a.y;
                }
                if (outF) {
                    long obase = ((long)b*CO + co) * Lout + t;
                    *(float2*)&outF[obase] = make_float2(x0, x1);
                }
                if (outHi) {
                    float p0 = __shfl_xor_sync(0xffffffffu, x0, 4);
                    float p1 = __shfl_xor_sync(0xffffffffu, x1, 4);
                    if (!(lane & 4)) {
                        unsigned a0h, a0l, b0h, b0l, a1h, a1l, b1h, b1l;
                        split_bf16(x0, a0h, a0l); split_bf16(p0, b0h, b0l);
                        split_bf16(x1, a1h, a1l); split_bf16(p1, b1h, b1l);
                        long pb = ((long)b*(CO >> 1) + (co >> 1))*Lout + t;
                        *(uint2*)&outHi[pb] = make_uint2(a0h | (b0h << 16), a1h | (b1h << 16));
                        *(uint2*)&outLo[pb] = make_uint2(a0l | (b0l << 16), a1l | (b1l << 16));
                    }
                }
                if (poolHi) {
                    float avg = 0.5f*(x0 + x1);
                    float pav = __shfl_xor_sync(0xffffffffu, avg, 4);
                    if (!(lane & 4)) {
                        unsigned ah, al, ph, pl;
                        split_bf16(avg, ah, al); split_bf16(pav, ph, pl);
                        long pb = ((long)b*(CO >> 1) + (co >> 1))*(Lout >> 1) + (t >> 1);
                        poolHi[pb] = ah | (ph << 16);
                        poolLo[pb] = al | (pl << 16);
                    }
                }
            }
        }
    }
}

template<int KW, int STRIDE, int TT, int CB2>
static void launch_conv(dim3 grid,
    const unsigned* wf, const unsigned* inHi, const unsigned* inLo,
    const float* scale, const float* bias, const float* addb,
    float* outF, unsigned* outHi, unsigned* outLo, unsigned* poolHi, unsigned* poolLo,
    int CI, int CO, int Lin, int Lout, int pad, int dorelu, long inBS)
{
    conv_mma<KW,STRIDE,TT,CB2><<<grid, 256>>>(wf, inHi, inLo, scale, bias, addb,
        outF, outHi, outLo, poolHi, poolLo, CI, CO, Lin, Lout, pad, dorelu, inBS);
}

// ---------------- fused rc2 (KW=9,s=1) + rid (KW=1), cp.async staging ----------------
template<int TT, int CB2>
__global__ void __launch_bounds__(256, 2) conv_mma_fused(
    const unsigned* __restrict__ wf9, const unsigned* __restrict__ wf1,
    const unsigned* __restrict__ bHi, const unsigned* __restrict__ bLo,
    const unsigned* __restrict__ pHi, const unsigned* __restrict__ pLo,
    const float* __restrict__ scale, const float* __restrict__ bias,
    unsigned* __restrict__ outHi, unsigned* __restrict__ outLo,
    unsigned* __restrict__ poolHi, unsigned* __restrict__ poolLo,
    int Lh, long inBS)
{
    constexpr int WIN = TT + 8;
    constexpr int NN  = TT / 16;
    constexpr int W   = CB2*10;
    __shared__ __align__(16) unsigned sBH[2][WIN][W], sBL[2][WIN][W];
    __shared__ __align__(16) unsigned sPH[2][TT][W],  sPL[2][TT][W];

    const int tid  = threadIdx.x;
    const int lane = tid & 31;
    const int wid  = tid >> 5;
    const int wco  = wid & 3;
    const int wt   = wid >> 2;
    const int t0   = blockIdx.x * TT;
    const int co0  = blockIdx.y * 128;
    const int b    = blockIdx.z;
    const int NCH  = 16;
    const int nst  = NCH / CB2;
    const long ct0 = (co0 >> 4) + wco*2;
    const unsigned* bHib = bHi + (long)b * inBS;
    const unsigned* bLob = bLo + (long)b * inBS;
    const unsigned* pHib = pHi + (long)b * inBS;
    const unsigned* pLob = pLo + (long)b * inBS;

    float acc9[2][NN][4] = {};
    float acc1[2][NN][4] = {};

    auto stage = [&](int buf, int grp) {
        int cp0 = grp * CB2 * 8;
        for (int idx = tid; idx < CB2*8*WIN; idx += 256) {
            int c2 = idx / (8*WIN);
            int rem = idx - c2*8*WIN;
            int pr = rem / WIN, pos = rem - pr*WIN;
            int j = c2*10 + ((pr < 4) ? (2*pr) : (2*(pr-4)+1));
            long row = (long)(cp0 + c2*8 + pr)*Lh;
            int g = t0 - 4 + pos;
            bool ok = (g >= 0 && g < Lh);
            long gi = row + (ok ? g : 0);
            cp4(&sBH[buf][pos][j], bHib + gi, ok);
            cp4(&sBL[buf][pos][j], bLob + gi, ok);
            if (pos < TT) {
                cp4(&sPH[buf][pos][j], pHib + row + t0 + pos, true);
                cp4(&sPL[buf][pos][j], pLob + row + t0 + pos, true);
            }
        }
        cp_commit();
    };

    stage(0, 0);
    cp_wait<0>();
    __syncthreads();
    for (int s = 0; s < nst; s++) {
        int cur = s & 1;
        if (s + 1 < nst) stage(cur ^ 1, s + 1);
        #pragma unroll
        for (int c2 = 0; c2 < CB2; c2++) {
            int ch = s*CB2 + c2;
            #pragma unroll
            for (int k = 0; k < 9; k++) {
                const uint4* af0 = (const uint4*)(wf9 + (((ct0*NCH + ch)*9 + k) << 8) + (lane << 3));
                const uint4* af1 = (const uint4*)(wf9 + ((((ct0+1)*NCH + ch)*9 + k) << 8) + (lane << 3));
                uint4 ahi0 = af0[0], alo0 = af0[1];
                uint4 ahi1 = af1[0], alo1 = af1[1];
                #pragma unroll
                for (int n = 0; n < NN; n++) {
                    int tl = wt*(TT/2) + n*8 + (lane >> 2);
                    int pos = tl + k;
                    int j2 = c2*10 + (lane & 3)*2;
                    uint2 bh = *(const uint2*)&sBH[cur][pos][j2];
                    uint2 bl = *(const uint2*)&sBL[cur][pos][j2];
                    mma16816(acc9[0][n], ahi0.x, ahi0.y, ahi0.z, ahi0.w, bh.x, bh.y);
                    mma16816(acc9[0][n], alo0.x, alo0.y, alo0.z, alo0.w, bh.x, bh.y);
                    mma16816(acc9[0][n], ahi0.x, ahi0.y, ahi0.z, ahi0.w, bl.x, bl.y);
                    mma16816(acc9[1][n], ahi1.x, ahi1.y, ahi1.z, ahi1.w, bh.x, bh.y);
                    mma16816(acc9[1][n], alo1.x, alo1.y, alo1.z, alo1.w, bh.x, bh.y);
                    mma16816(acc9[1][n], ahi1.x, ahi1.y, ahi1.z, ahi1.w, bl.x, bl.y);
                }
            }
            {
                const uint4* af0 = (const uint4*)(wf1 + (((ct0*NCH + ch)) << 8) + (lane << 3));
                const uint4* af1 = (const uint4*)(wf1 + ((((ct0+1)*NCH + ch)) << 8) + (lane << 3));
                uint4 ahi0 = af0[0], alo0 = af0[1];
                uint4 ahi1 = af1[0], alo1 = af1[1];
                #pragma unroll
                for (int n = 0; n < NN; n++) {
                    int pos = wt*(TT/2) + n*8 + (lane >> 2);
                    int j2 = c2*10 + (lane & 3)*2;
                    uint2 bh = *(const uint2*)&sPH[cur][pos][j2];
                    uint2 bl = *(const uint2*)&sPL[cur][pos][j2];
                    mma16816(acc1[0][n], ahi0.x, ahi0.y, ahi0.z, ahi0.w, bh.x, bh.y);
                    mma16816(acc1[0][n], alo0.x, alo0.y, alo0.z, alo0.w, bh.x, bh.y);
                    mma16816(acc1[0][n], ahi0.x, ahi0.y, ahi0.z, ahi0.w, bl.x, bl.y);
                    mma16816(acc1[1][n], ahi1.x, ahi1.y, ahi1.z, ahi1.w, bh.x, bh.y);
                    mma16816(acc1[1][n], alo1.x, alo1.y, alo1.z, alo1.w, bh.x, bh.y);
                    mma16816(acc1[1][n], ahi1.x, ahi1.y, ahi1.z, ahi1.w, bl.x, bl.y);
                }
            }
        }
        if (s + 1 < nst) cp_wait<0>();
        __syncthreads();
    }

    #pragma unroll
    for (int q = 0; q < 2; q++) {
        #pragma unroll
        for (int n = 0; n < NN; n++) {
            int t = t0 + wt*(TT/2) + n*8 + (lane & 3)*2;
            #pragma unroll
            for (int h = 0; h < 2; h++) {
                int co = co0 + wco*32 + q*16 + (lane >> 2) + h*8;
                float sc = scale[co];
                float bb = bias[co];
                float x0 = acc9[q][n][2*h]   * sc + bb;
                float x1 = acc9[q][n][2*h+1] * sc + bb;
                x0 = x0 >= 0.f ? x0 : NEG*x0;
                x1 = x1 >= 0.f ? x1 : NEG*x1;
                x0 += acc1[q][n][2*h];
                x1 += acc1[q][n][2*h+1];
                float p0 = __shfl_xor_sync(0xffffffffu, x0, 4);
                float p1 = __shfl_xor_sync(0xffffffffu, x1, 4);
                float avg = 0.5f*(x0 + x1);
                float pav = __shfl_xor_sync(0xffffffffu, avg, 4);
                if (!(lane & 4)) {
                    unsigned a0h, a0l, b0h, b0l, a1h, a1l, b1h, b1l;
                    split_bf16(x0, a0h, a0l); split_bf16(p0, b0h, b0l);
                    split_bf16(x1, a1h, a1l); split_bf16(p1, b1h, b1l);
                    long pb = ((long)b*128 + (co >> 1))*Lh + t;
                    *(uint2*)&outHi[pb] = make_uint2(a0h | (b0h << 16), a1h | (b1h << 16));
                    *(uint2*)&outLo[pb] = make_uint2(a0l | (b0l << 16), a1l | (b1l << 16));
                    unsigned ah, al, ph, pl;
                    split_bf16(avg, ah, al); split_bf16(pav, ph, pl);
                    long qb = ((long)b*128 + (co >> 1))*(Lh >> 1) + (t >> 1);
                    poolHi[qb] = ah | (ph << 16);
                    poolLo[qb] = al | (pl << 16);
                }
            }
        }
    }
}

// ---------------- scalar implicit-GEMM conv1d (CI=1 layers) ----------------
template<int KW, int STRIDE, int CB>
__global__ void __launch_bounds__(256, 2) conv_gemm(
    const float* __restrict__ wT, const float* __restrict__ in,
    const float* __restrict__ scale, const float* __restrict__ bias,
    float* __restrict__ out,
    int CI, int CO, int Lin, int Lout, int pad, int dorelu, long inBS)
{
    constexpr int WIN  = 64*STRIDE + KW - 1;
    constexpr int WINP = (WIN + 11) & ~3;
    constexpr int RW   = 3*STRIDE + KW;
    constexpr int NV   = (RW + 3) / 4;
    __shared__ __align__(16) float sW[2][CB*KW*64];
    __shared__ __align__(16) float sIn[2][CB][WINP];

    const int tid = threadIdx.x;
    const int tx = tid & 15, ty = tid >> 4;
    const int t0 = blockIdx.x * 64, co0 = blockIdx.y * 64;
    const int b  = blockIdx.z;
    const float* inb = in + (long)b * inBS;
    const long wstride = (long)KW * 64;
    const float* wbase = wT + (long)blockIdx.y * CI * wstride;

    ull acc01[4], acc23[4];
    #pragma unroll
    for (int j = 0; j < 4; j++) { acc01[j] = 0ull; acc23[j] = 0ull; }

    const int nst = CI / CB;
    auto stage = [&](int buf, int cib) {
        const float4* ws = (const float4*)(wbase + (long)cib * wstride);
        float4* wd = (float4*)sW[buf];
        for (int idx = tid; idx < CB*KW*16; idx += 256) wd[idx] = ws[idx];
        for (int idx = tid; idx < CB*WIN; idx += 256) {
            int c = idx / WIN, w = idx - c*WIN;
            int g = t0*STRIDE - pad + w;
            sIn[buf][c][w] = (g >= 0 && g < Lin) ? __ldg(&inb[(long)(cib+c)*Lin + g]) : 0.f;
        }
    };

    stage(0, 0);
    __syncthreads();
    for (int s = 0; s < nst; s++) {
        int cur = s & 1;
        if (s + 1 < nst) stage(cur ^ 1, (s + 1) * CB);
        #pragma unroll
        for (int c = 0; c < CB; c++) {
            float4 wv4[NV];
            const float4* ip = (const float4*)&sIn[cur][c][tx*4*STRIDE];
            #pragma unroll
            for (int v = 0; v < NV; v++) wv4[v] = ip[v];
            const float* wfp = (const float*)wv4;
            ull bc[RW];
            #pragma unroll
            for (int m = 0; m < RW; m++) bc[m] = pk2(wfp[m], wfp[m]);
            const float* wrow = sW[cur] + c*KW*64 + ty*4;
            #pragma unroll
            for (int k = 0; k < KW; k++) {
                ulonglong2 wv = *(const ulonglong2*)(wrow + k*64);
                #pragma unroll
                for (int j = 0; j < 4; j++) {
                    acc01[j] = ffma2(wv.x, bc[j*STRIDE + k], acc01[j]);
                    acc23[j] = ffma2(wv.y, bc[j*STRIDE + k], acc23[j]);
                }
            }
        }
        __syncthreads();
    }

    float r[4][4];
    #pragma unroll
    for (int j = 0; j < 4; j++) { upk2(acc01[j], r[0][j], r[1][j]); upk2(acc23[j], r[2][j], r[3][j]); }
    #pragma unroll
    for (int i = 0; i < 4; i++) {
        int co = co0 + ty*4 + i;
        float sc = scale ? scale[co] : 1.f;
        float bb = bias  ? bias[co]  : 0.f;
        long obase = ((long)b*CO + co) * Lout + t0 + tx*4;
        float4 v;
        v.x = r[i][0]*sc + bb; v.y = r[i][1]*sc + bb;
        v.z = r[i][2]*sc + bb; v.w = r[i][3]*sc + bb;
        if (dorelu) {
            v.x = v.x >= 0.f ? v.x : NEG*v.x; v.y = v.y >= 0.f ? v.y : NEG*v.y;
            v.z = v.z >= 0.f ? v.z : NEG*v.z; v.w = v.w >= 0.f ? v.w : NEG*v.w;
        }
        *(float4*)&out[obase] = v;
    }
}

// ---------------- attention per (batch, head): writes ATT pair planes ----------------
__global__ void __launch_bounds__(128) attn_kernel(const float* __restrict__ qkv,
                                                   unsigned* __restrict__ ohi,
                                                   unsigned* __restrict__ olo)
{
    __shared__ float q[32][64], kk[32][64], vv[32][64];
    __shared__ float att[64][65];
    int bh = blockIdx.x; int b = bh >> 3, h = bh & 7;
    const float* base = qkv + (long)b*768*64 + (long)h*32*64;
    int tid = threadIdx.x;
    for (int idx = tid; idx < 2048; idx += 128) {
        int d = idx >> 6, s = idx & 63;
        q [d][s] = base[d*64 + s];
        kk[d][s] = base[256*64 + d*64 + s];
        vv[d][s] = base[512*64 + d*64 + s];
    }
    __syncthreads();
    for (int e = tid; e < 4096; e += 128) {
        int qs = e >> 6, ks = e & 63;
        float s = 0.f;
        #pragma unroll
        for (int d = 0; d < 32; d++) s = fmaf(q[d][qs], kk[d][ks], s);
        att[qs][ks] = s * 0.17677669529663687f;
    }
    __syncthreads();
    if (tid < 64) {
        float m = -1e30f;
        for (int ks = 0; ks < 64; ks++) m = fmaxf(m, att[tid][ks]);
        float sum = 0.f;
        for (int ks = 0; ks < 64; ks++) { float e = expf(att[tid][ks] - m); att[tid][ks] = e; sum += e; }
        float inv = 1.f / sum;
        for (int ks = 0; ks < 64; ks++) att[tid][ks] *= inv;
    }
    __syncthreads();
    for (int e = tid; e < 1024; e += 128) {
        int m = e >> 6, qs = e & 63;
        float s0 = 0.f, s1 = 0.f;
        #pragma unroll
        for (int ks = 0; ks < 64; ks++) {
            float a = att[qs][ks];
            s0 = fmaf(a, vv[2*m][ks],   s0);
            s1 = fmaf(a, vv[2*m+1][ks], s1);
        }
        unsigned h0, l0, h1, l1;
        split_bf16(s0, h0, l0);
        split_bf16(s1, h1, l1);
        long idx = ((long)b*128 + h*16 + m)*64 + qs;
        ohi[idx] = h0 | (h1 << 16);
        olo[idx] = l0 | (l1 << 16);
    }
}

__global__ void max_t_kernel(const float* __restrict__ in, float* __restrict__ out)
{
    int b = blockIdx.x, c = threadIdx.x;
    const float* r = in + ((long)b*256 + c) * 64;
    float m = r[0];
    #pragma unroll
    for (int t = 1; t < 64; t++) m = fmaxf(m, r[t]);
    out[b*256 + c] = m;
}

__global__ void group_max_kernel(const float* __restrict__ in, float* __restrict__ out, int GS)
{
    int row = blockIdx.x; int g = threadIdx.x; int G = blockDim.x;
    const float* r = in + (long)row*G*GS + (long)g*GS;
    float m = r[0];
    for (int j = 1; j < GS; j++) m = fmaxf(m, r[j]);
    out[(long)row*G + g] = m;
}

// ---------------- dense: one warp per (batch, output) ----------------
__global__ void __launch_bounds__(256) dense_kernel(const float* __restrict__ in,
                                                    const float* __restrict__ w,
                                                    const float* __restrict__ bias,
                                                    float* __restrict__ out,
                                                    int IN, int OUT, int dorelu)
{
    int wid = threadIdx.x >> 5, lane = threadIdx.x & 31;
    int gid = blockIdx.x*8 + wid;
    int b = gid / OUT, o = gid - b*OUT;
    if (b >= 64) return;
    const float* iv = in + (long)b*IN;
    const float* wr = w + (long)o*IN;
    float s = 0.f;
    for (int i = lane; i < IN; i += 32) s = fmaf(iv[i], wr[i], s);
    #pragma unroll
    for (int off = 16; off > 0; off >>= 1) s += __shfl_down_sync(0xffffffffu, s, off);
    if (lane == 0) {
        if (bias) s += bias[o];
        if (dorelu) s = (s >= 0.f) ? s : NEG*s;
        out[b*OUT + o] = s;
    }
}

__global__ void twiddle_kernel()
{
    int i = blockIdx.x*256 + threadIdx.x;
    if (i < 4096) {
        double a = -2.0 * 3.14159265358979323846 * (double)i / 4096.0;
        g_tw[i] = make_float2((float)cos(a), (float)sin(a));
    }
}

__global__ void __launch_bounds__(256) fft_freq_kernel(const float* __restrict__ x,
                                                       const float* __restrict__ fw,
                                                       const float* __restrict__ fb,
                                                       float* __restrict__ out)
{
    __shared__ float2 stw[4096];
    __shared__ float smag[256];
    __shared__ float sred[256];
    int b = blockIdx.x, tid = threadIdx.x;
    for (int i = tid; i < 4096; i += 256) stw[i] = g_tw[i];
    const float* xr = x + ((long)b*12 + 1) * 4096;
    __syncthreads();
    int k = 50 + tid;
    float re0 = 0.f, im0 = 0.f, re1 = 0.f, im1 = 0.f;
    for (int n = 0; n < 4096; n += 4) {
        float4 xv = *(const float4*)&xr[n];
        int i0 = (k*n) & 4095;
        int i1 = (i0 + k) & 4095;
        int i2 = (i0 + 2*k) & 4095;
        int i3 = (i0 + 3*k) & 4095;
        float2 c0 = stw[i0], c1 = stw[i1], c2 = stw[i2], c3 = stw[i3];
        re0 = fmaf(xv.x, c0.x, re0); im0 = fmaf(xv.x, c0.y, im0);
        re1 = fmaf(xv.y, c1.x, re1); im1 = fmaf(xv.y, c1.y, im1);
        re0 = fmaf(xv.z, c2.x, re0); im0 = fmaf(xv.z, c2.y, im0);
        re1 = fmaf(xv.w, c3.x, re1); im1 = fmaf(xv.w, c3.y, im1);
    }
    float re = re0 + re1, im = im0 + im1;
    float mag = sqrtf(re*re + im*im);
    smag[tid] = mag; sred[tid] = mag;
    __syncthreads();
    for (int s = 128; s > 0; s >>= 1) {
        if (tid < s) sred[tid] = fmaxf(sred[tid], sred[tid+s]);
        __syncthreads();
    }
    float mx = sred[0];
    smag[tid] = (mx > 0.f) ? mag/mx : mag;
    __syncthreads();
    if (tid < 32) {
        float s = fb[tid];
        const float* wr = fw + tid*256;
        for (int j = 0; j < 256; j++) s = fmaf(smag[j], wr[j], s);
        out[b*32 + tid] = (s >= 0.f) ? s : NEG*s;
    }
}

__global__ void final_kernel(const float* __restrict__ xm, const float* __restrict__ l,
                             const float* __restrict__ fq, const float* __restrict__ f2,
                             const float* __restrict__ p2, const float* __restrict__ fcw,
                             const float* __restrict__ fcb, float* __restrict__ out)
{
    __shared__ float comb[396];
    int b = blockIdx.x, tid = threadIdx.x;
    for (int i = tid; i < 256; i += 128) comb[i] = xm[b*256 + i];
    if (tid < 12) comb[256 + tid] = l[b*12 + tid];
    if (tid < 32) comb[268 + tid] = fq[b*32 + tid];
    if (tid < 64) comb[300 + tid] = f2[b*64 + tid];
    if (tid < 32) comb[364 + tid] = p2[b*32 + tid];
    __syncthreads();
    if (tid < 27) {
        float s = fcb[tid];
        const float* wr = fcw + tid*396;
        for (int j = 0; j < 396; j++) s = fmaf(comb[j], wr[j], s);
        out[b*27 + tid] = s;
        out[64*27 + b*27 + tid] = 1.f / (1.f + expf(-s));
    }
}

// ---------------- host launch ----------------
extern "C" void kernel_launch(void* const* d_in, const int* in_sizes, int n_in,
                              void* d_out, int out_size)
{
    (void)in_sizes; (void)n_in; (void)out_size;
    const float* x      = (const float*)d_in[0];
    const float* l      = (const float*)d_in[1];
    const float* conv_w = (const float*)d_in[2];
    const float* bn0    = (const float*)d_in[3];
    const float* rc1    = (const float*)d_in[4];
    const float* rbn1   = (const float*)d_in[5];
    const float* rc2    = (const float*)d_in[6];
    const float* rbn2   = (const float*)d_in[7];
    const float* rid    = (const float*)d_in[8];
    const float* miw    = (const float*)d_in[9];
    const float* mib    = (const float*)d_in[10];
    const float* mow    = (const float*)d_in[11];
    const float* mob    = (const float*)d_in[12];
    const float* fw     = (const float*)d_in[13];
    const float* fbv    = (const float*)d_in[14];
    const float* fbn    = (const float*)d_in[15];
    const float* pw     = (const float*)d_in[16];
    const float* pbv    = (const float*)d_in[17];
    const float* pbn    = (const float*)d_in[18];
    const float* wflut2 = (const float*)d_in[19];
    const float* wpvc2  = (const float*)d_in[20];
    const float* freqw  = (const float*)d_in[21];
    const float* freqb  = (const float*)d_in[22];
    const float* fcw    = (const float*)d_in[23];
    const float* fcb    = (const float*)d_in[24];

    unsigned *A, *Bf, *P0, *ATT, *WF;
    float *C, *QKV, *HM, *XM, *FV, *PV, *F2, *P2, *FQ, *BN, *WT;
    cudaGetSymbolAddress((void**)&A,   g_bufA);
    cudaGetSymbolAddress((void**)&Bf,  g_bufB);
    cudaGetSymbolAddress((void**)&P0,  g_bufP);
    cudaGetSymbolAddress((void**)&C,   g_bufC);
    cudaGetSymbolAddress((void**)&QKV, g_qkv);
    cudaGetSymbolAddress((void**)&ATT, g_att);
    cudaGetSymbolAddress((void**)&HM,  g_hm);
    cudaGetSymbolAddress((void**)&XM,  g_xmain);
    cudaGetSymbolAddress((void**)&FV,  g_fvec);
    cudaGetSymbolAddress((void**)&PV,  g_pvec);
    cudaGetSymbolAddress((void**)&F2,  g_f2);
    cudaGetSymbolAddress((void**)&P2,  g_p2);
    cudaGetSymbolAddress((void**)&FQ,  g_freq);
    cudaGetSymbolAddress((void**)&BN,  g_bn);
    cudaGetSymbolAddress((void**)&WT,  g_wT);
    cudaGetSymbolAddress((void**)&WF,  g_wf);

    unsigned* XP = (unsigned*)C;   // conv0 packed input planes
    unsigned* P1 = (unsigned*)C;   // P pong (free after last separate-rid layer)

    prep_kernel<<<1, 256>>>(bn0, rbn1, rbn2, fbn, fbv, pbn, pbv);
    twiddle_kernel<<<16, 256>>>();
    pack_x_kernel<<<8192, 256>>>(x, XP, XP + PL_X);

    auto wt = [&](const float* src, long off, int CO, int CI, int KW) {
        long tot = (long)CO*CI*KW;
        wtrans_kernel<<<(unsigned)((tot + 255)/256), 256>>>(src, WT + off, CI, KW, tot);
    };
    wt(fw, O_FLUT, 64, 1, 15);
    wt(pw, O_PVC,  64, 1, 9);

    auto wfp = [&](const float* src, long off, int CO, int CIsrc, int CIpad, int KW) {
        long tot = (long)(CO/16)*(CIpad/16)*KW*128;
        wfrag_kernel<<<(unsigned)((tot + 255)/256), 256>>>(src, WF + off, CIsrc, KW, CIpad/16, tot);
    };
    for (int i = 0; i < 5; i++) {
        wfp(rc1 + (long)i*256*256*9, WF_RC1 + (long)i*589824, 256, 256, 256, 9);
        wfp(rc2 + (long)i*256*256*9, WF_RC2 + (long)i*589824, 256, 256, 256, 9);
        wfp(rid + (long)i*256*256,   WF_RID + (long)i*65536,  256, 256, 256, 1);
    }
    wfp(miw,    WF_MHAIN,  768, 256, 256, 1);
    wfp(mow,    WF_MHAOUT, 256, 256, 256, 1);
    wfp(conv_w, WF_CONV0,  256,  12,  16, 15);

    // conv0: mma path -> A planes + pooled P planes (into P0)
    launch_conv<15,2,64,1>(dim3(32,2,64), WF+WF_CONV0, XP, XP + PL_X, BN+0, BN+256, nullptr,
                           nullptr, A, A + PL_A, P0, P0 + PL_P,
                           16, 256, 4096, 2048, 7, 1, 8L*4096);

    unsigned* Pcur = P0;
    unsigned* Palt = P1;
    int L = 2048;
    for (int i = 0; i < 5; i++) {
        int Lh = L/2;
        if (Lh >= 256) {
            launch_conv<9,2,128,1>(dim3(Lh/128,2,64), WF+WF_RC1 + (long)i*589824, A, A + PL_A,
                BN+512+i*256, BN+1792+i*256, nullptr, nullptr, Bf, Bf + PL_B, nullptr, nullptr,
                256, 256, L, Lh, 4, 1, 128L*L);
            launch_conv<1,1,128,2>(dim3(Lh/128,2,64), WF+WF_RID + (long)i*65536, Pcur, Pcur + PL_P,
                nullptr, nullptr, nullptr, C, nullptr, nullptr, nullptr, nullptr,
                256, 256, Lh, Lh, 0, 0, 128L*Lh);
            launch_conv<9,1,128,2>(dim3(Lh/128,2,64), WF+WF_RC2 + (long)i*589824, Bf, Bf + PL_B,
                BN+3072+i*256, BN+4352+i*256, C, nullptr, A, A + PL_A, Pcur, Pcur + PL_P,
                256, 256, Lh, Lh, 4, 1, 128L*Lh);
        } else {
            if (Lh == 128)
                launch_conv<9,2,64,1>(dim3(2,2,64), WF+WF_RC1 + (long)i*589824, A, A + PL_A,
                    BN+512+i*256, BN+1792+i*256, nullptr, nullptr, Bf, Bf + PL_B, nullptr, nullptr,
                    256, 256, L, Lh, 4, 1, 128L*L);
            else
                launch_conv<9,2,32,1>(dim3(2,2,64), WF+WF_RC1 + (long)i*589824, A, A + PL_A,
                    BN+512+i*256, BN+1792+i*256, nullptr, nullptr, Bf, Bf + PL_B, nullptr, nullptr,
                    256, 256, L, Lh, 4, 1, 128L*L);
            conv_mma_fused<64,2><<<dim3(Lh/64,2,64), 256>>>(
                WF+WF_RC2 + (long)i*589824, WF+WF_RID + (long)i*65536,
                Bf, Bf + PL_B, Pcur, Pcur + PL_P,
                BN+3072+i*256, BN+4352+i*256,
                A, A + PL_A, Palt, Palt + PL_P, Lh, 128L*Lh);
            unsigned* tmp = Pcur; Pcur = Palt; Palt = tmp;
        }
        L = Lh;
    }

    // MHA
    launch_conv<1,1,64,2>(dim3(1,6,64), WF+WF_MHAIN, A, A + PL_A, nullptr, mib, nullptr,
                          QKV, nullptr, nullptr, nullptr, nullptr,
                          256, 768, 64, 64, 0, 0, 128L*64);
    attn_kernel<<<512, 128>>>(QKV, ATT, ATT + PL_ATT);
    launch_conv<1,1,64,2>(dim3(1,2,64), WF+WF_MHAOUT, ATT, ATT + PL_ATT, nullptr, mob, nullptr,
                          HM, nullptr, nullptr, nullptr, nullptr,
                          256, 256, 64, 64, 0, 0, 128L*64);
    max_t_kernel<<<64, 256>>>(HM, XM);

    // FLUT path (float scratch overlays Bf buffer)
    conv_gemm<15,2,1><<<dim3(32,1,64), 256>>>(WT+O_FLUT, x + 4096, BN+5632, BN+5696, (float*)Bf,
                                              1, 64, 4096, 2048, 7, 1, 12L*4096);
    group_max_kernel<<<64*64, 64>>>((const float*)Bf, FV, 32);
    dense_kernel<<<512, 256>>>(FV, wflut2, nullptr, F2, 4096, 64, 1);

    // PVC path
    conv_gemm<9,2,1><<<dim3(32,1,64), 256>>>(WT+O_PVC, x + 4096, BN+5760, BN+5824, (float*)Bf,
                                             1, 64, 4096, 2048, 4, 1, 12L*4096);
    group_max_kernel<<<64*64, 32>>>((const float*)Bf, PV, 64);
    dense_kernel<<<256, 256>>>(PV, wpvc2, nullptr, P2, 2048, 32, 1);

    // FFT + freq dense
    fft_freq_kernel<<<64, 256>>>(x, freqw, freqb, FQ);

    // concat + FC + sigmoid
    final_kernel<<<64, 128>>>(XM, l, FQ, F2, P2, fcw, fcb, (float*)d_out);
}

// round 17
// speedup vs baseline: 1.1461x; 1.0351x over previous
#include <cuda_runtime.h>
#include <cuda_bf16.h>
#include <math.h>

#define NEG 0.01f
typedef unsigned long long ull;

// ---------------- packed f32x2 helpers (scalar conv path) ----------------
__device__ __forceinline__ ull pk2(float lo, float hi) {
    ull r; asm("mov.b64 %0,{%1,%2};" : "=l"(r) : "f"(lo), "f"(hi)); return r;
}
__device__ __forceinline__ void upk2(ull v, float& lo, float& hi) {
    asm("mov.b64 {%0,%1},%2;" : "=f"(lo), "=f"(hi) : "l"(v));
}
__device__ __forceinline__ ull ffma2(ull a, ull b, ull c) {
    ull d; asm("fma.rn.f32x2 %0,%1,%2,%3;" : "=l"(d) : "l"(a), "l"(b), "l"(c)); return d;
}

// ---------------- bf16 hi/lo split ----------------
__device__ __forceinline__ void split_bf16(float v, unsigned& h, unsigned& l) {
    __nv_bfloat16 hb = __float2bfloat16(v);
    float r = v - __bfloat162float(hb);
    __nv_bfloat16 lb = __float2bfloat16(r);
    h = (unsigned)__bfloat16_as_ushort(hb);
    l = (unsigned)__bfloat16_as_ushort(lb);
}

__device__ __forceinline__ void mma16816(float* c, unsigned a0, unsigned a1, unsigned a2, unsigned a3,
                                         unsigned b0, unsigned b1) {
    asm volatile("mma.sync.aligned.m16n8k16.row.col.f32.bf16.bf16.f32 "
        "{%0,%1,%2,%3}, {%4,%5,%6,%7}, {%8,%9}, {%0,%1,%2,%3};"
        : "+f"(c[0]), "+f"(c[1]), "+f"(c[2]), "+f"(c[3])
        : "r"(a0), "r"(a1), "r"(a2), "r"(a3), "r"(b0), "r"(b1));
}

// ---------------- cp.async helpers ----------------
__device__ __forceinline__ void cp4(unsigned* dst, const unsigned* src, bool pred) {
    unsigned d = (unsigned)__cvta_generic_to_shared(dst);
    asm volatile("cp.async.ca.shared.global [%0], [%1], 4, %2;"
                 :: "r"(d), "l"(src), "r"(pred ? 4 : 0));
}
__device__ __forceinline__ void cp_commit() {
    asm volatile("cp.async.commit_group;");
}
template<int N>
__device__ __forceinline__ void cp_wait() {
    asm volatile("cp.async.wait_group %0;" :: "n"(N));
}

// ---------------- scratch ----------------
__device__ unsigned g_bufA[64L*256*2048];   // A: hi @0, lo @PL_A
__device__ unsigned g_bufB[64L*256*1024];   // Bf planes (main chain)
__device__ unsigned g_bufP[64L*256*1024];   // P planes ping
__device__ float    g_bufC[64L*256*1024];   // conv0 packed input / rid float out / P pong
__device__ float    g_bufS[2][64L*64*2048]; // flut/pvc float scratch (side streams)
__device__ float    g_qkv [64L*768*64];
__device__ unsigned g_att [64L*256*64];     // ATT planes
__device__ float    g_hm  [64L*256*64];
__device__ float g_xmain[64*256];
__device__ float g_fvec[64*4096];
__device__ float g_pvec[64*2048];
__device__ float g_f2[64*64];
__device__ float g_p2[64*32];
__device__ float g_freq[64*32];
__device__ float2 g_tw[4096];
__device__ float g_bn[8192];
__device__ float g_wT[4096];             // scalar-path weights (flut/pvc)
__device__ unsigned g_wf[6549504];       // mma fragment weights (hi/lo bf16)

#define PL_A   (64L*128*2048)
#define PL_B   (64L*128*1024)
#define PL_P   (64L*128*1024)
#define PL_ATT (64L*128*64)
#define PL_X   (64L*8*4096)

#define O_FLUT    0L
#define O_PVC     960L

#define WF_RC1    0L
#define WF_RC2    2949120L
#define WF_RID    5898240L
#define WF_MHAIN  6225920L
#define WF_MHAOUT 6422528L
#define WF_CONV0  6488064L

// ---------------- BN folding ----------------
__global__ void prep_kernel(const float* __restrict__ bn0,
                            const float* __restrict__ rbn1,
                            const float* __restrict__ rbn2,
                            const float* __restrict__ fbn, const float* __restrict__ fb,
                            const float* __restrict__ pbn, const float* __restrict__ pb)
{
    int c = threadIdx.x;
    if (c < 256) {
        {
            float g = bn0[c], b = bn0[256+c], m = bn0[512+c], v = bn0[768+c];
            float s = g * rsqrtf(v + 1e-5f);
            g_bn[c] = s; g_bn[256+c] = b - m*s;
        }
        for (int i = 0; i < 5; i++) {
            const float* p1 = rbn1 + i*1024;
            float g = p1[c], b = p1[256+c], m = p1[512+c], v = p1[768+c];
            float s = g * rsqrtf(v + 1e-5f);
            g_bn[512 + i*256 + c] = s; g_bn[1792 + i*256 + c] = b - m*s;
            const float* p2 = rbn2 + i*1024;
            g = p2[c]; b = p2[256+c]; m = p2[512+c]; v = p2[768+c];
            s = g * rsqrtf(v + 1e-5f);
            g_bn[3072 + i*256 + c] = s; g_bn[4352 + i*256 + c] = b - m*s;
        }
    }
    if (c < 64) {
        float g = fbn[c], b = fbn[64+c], m = fbn[128+c], v = fbn[192+c];
        float s = g * rsqrtf(v + 1e-5f);
        g_bn[5632+c] = s; g_bn[5696+c] = (fb[c] - m)*s + b;
        g = pbn[c]; b = pbn[64+c]; m = pbn[128+c]; v = pbn[192+c];
        s = g * rsqrtf(v + 1e-5f);
        g_bn[5760+c] = s; g_bn[5824+c] = (pb[c] - m)*s + b;
    }
}

// ---------------- pack x for conv0: pair planes, 12->16 padded channels ----------------
__global__ void pack_x_kernel(const float* __restrict__ x,
                              unsigned* __restrict__ xhi, unsigned* __restrict__ xlo)
{
    long i = (long)blockIdx.x*256 + threadIdx.x;
    if (i >= 64L*8*4096) return;
    int t = (int)(i & 4095);
    long r = i >> 12;
    int p = (int)(r & 7);
    int b = (int)(r >> 3);
    int c0 = 2*p, c1 = 2*p + 1;
    float v0 = (c0 < 12) ? x[((long)b*12 + c0)*4096 + t] : 0.f;
    float v1 = (c1 < 12) ? x[((long)b*12 + c1)*4096 + t] : 0.f;
    unsigned h0, l0, h1, l1;
    split_bf16(v0, h0, l0);
    split_bf16(v1, h1, l1);
    xhi[i] = h0 | (h1 << 16);
    xlo[i] = l0 | (l1 << 16);
}

// ---------------- weight transpose (scalar conv path) ----------------
__global__ void wtrans_kernel(const float* __restrict__ src, float* __restrict__ dst,
                              int CI, int KW, long total)
{
    long i = (long)blockIdx.x*256 + threadIdx.x;
    if (i >= total) return;
    int co64 = (int)(i & 63);
    long r = i >> 6;
    int k = (int)(r % KW); r /= KW;
    int ci = (int)(r % CI);
    long ct = r / CI;
    long co = ct*64 + co64;
    dst[i] = src[(co*CI + ci)*KW + k];
}

// ---------------- weight -> mma fragment (hi/lo bf16), CIsrc-padded ----------------
__global__ void wfrag_kernel(const float* __restrict__ src, unsigned* __restrict__ dst,
                             int CIsrc, int KW, int NCH, long total)
{
    long i = (long)blockIdx.x*256 + threadIdx.x;
    if (i >= total) return;
    int r    = (int)(i & 3);
    int lane = (int)((i >> 2) & 31);
    long rest = i >> 7;
    int k  = (int)(rest % KW); rest /= KW;
    int ch = (int)(rest % NCH);
    long ct = rest / NCH;
    int row = lane >> 2;
    int col = (lane & 3) * 2;
    if (r & 1) row += 8;
    if (r >= 2) col += 8;
    long co = ct*16 + row;
    int ci = ch*16 + col;
    float w0 = (ci     < CIsrc) ? src[(co*CIsrc + ci    )*KW + k] : 0.f;
    float w1 = (ci + 1 < CIsrc) ? src[(co*CIsrc + ci + 1)*KW + k] : 0.f;
    unsigned h0, l0, h1, l1;
    split_bf16(w0, h0, l0);
    split_bf16(w1, h1, l1);
    long base = (((ct*NCH + ch)*KW + k)*32 + lane)*8;
    dst[base + r]     = h0 | (h1 << 16);
    dst[base + 4 + r] = l0 | (l1 << 16);
}

// ---------------- tensor-core conv1d (bf16 split planes, fp32 acc, cp.async staging) ----------------
template<int KW, int STRIDE, int TT, int CB2>
__global__ void __launch_bounds__(256, 2) conv_mma(
    const unsigned* __restrict__ wf,
    const unsigned* __restrict__ inHi, const unsigned* __restrict__ inLo,
    const float* __restrict__ scale, const float* __restrict__ bias,
    const float* __restrict__ addb,
    float* __restrict__ outF,
    unsigned* __restrict__ outHi, unsigned* __restrict__ outLo,
    unsigned* __restrict__ poolHi, unsigned* __restrict__ poolLo,
    int CI, int CO, int Lin, int Lout, int pad, int dorelu, long inBS)
{
    constexpr int WIN = TT*STRIDE + KW - 1;
    constexpr int NN  = TT / 16;
    constexpr int W   = CB2*10;
    __shared__ __align__(16) unsigned sHi[2][WIN][W];
    __shared__ __align__(16) unsigned sLo[2][WIN][W];

    const int tid  = threadIdx.x;
    const int lane = tid & 31;
    const int wid  = tid >> 5;
    const int wco  = wid & 3;
    const int wt   = wid >> 2;
    const int t0   = blockIdx.x * TT;
    const int co0  = blockIdx.y * 128;
    const int b    = blockIdx.z;
    const int NCH  = CI >> 4;
    const int nst  = NCH / CB2;
    const long ct0 = (co0 >> 4) + wco*2;
    const unsigned* inHib = inHi + (long)b * inBS;
    const unsigned* inLob = inLo + (long)b * inBS;

    float acc[2][NN][4] = {};

    auto stage = [&](int buf, int grp) {
        int cp0 = grp * CB2 * 8;
        for (int idx = tid; idx < CB2*8*WIN; idx += 256) {
            int c2 = idx / (8*WIN);
            int rem = idx - c2*8*WIN;
            int pr = rem / WIN, pos = rem - pr*WIN;
            int j = c2*10 + ((pr < 4) ? (2*pr) : (2*(pr-4)+1));
            int g = t0*STRIDE - pad + pos;
            bool ok = (g >= 0 && g < Lin);
            long gi = (long)(cp0 + c2*8 + pr)*Lin + (ok ? g : 0);
            cp4(&sHi[buf][pos][j], inHib + gi, ok);
            cp4(&sLo[buf][pos][j], inLob + gi, ok);
        }
        cp_commit();
    };

    stage(0, 0);
    cp_wait<0>();
    __syncthreads();
    for (int s = 0; s < nst; s++) {
        int cur = s & 1;
        if (s + 1 < nst) stage(cur ^ 1, s + 1);
        #pragma unroll
        for (int c2 = 0; c2 < CB2; c2++) {
            int ch = s*CB2 + c2;
            #pragma unroll
            for (int k = 0; k < KW; k++) {
                const uint4* af0 = (const uint4*)(wf + (((ct0*NCH + ch)*KW + k) << 8) + (lane << 3));
                const uint4* af1 = (const uint4*)(wf + ((((ct0+1)*NCH + ch)*KW + k) << 8) + (lane << 3));
                uint4 ahi0 = af0[0], alo0 = af0[1];
                uint4 ahi1 = af1[0], alo1 = af1[1];
                #pragma unroll
                for (int n = 0; n < NN; n++) {
                    int tl = wt*(TT/2) + n*8 + (lane >> 2);
                    int pos = tl*STRIDE + k;
                    int j2 = c2*10 + (lane & 3)*2;
                    uint2 bh = *(const uint2*)&sHi[cur][pos][j2];
                    uint2 bl = *(const uint2*)&sLo[cur][pos][j2];
                    mma16816(acc[0][n], ahi0.x, ahi0.y, ahi0.z, ahi0.w, bh.x, bh.y);
                    mma16816(acc[0][n], alo0.x, alo0.y, alo0.z, alo0.w, bh.x, bh.y);
                    mma16816(acc[0][n], ahi0.x, ahi0.y, ahi0.z, ahi0.w, bl.x, bl.y);
                    mma16816(acc[1][n], ahi1.x, ahi1.y, ahi1.z, ahi1.w, bh.x, bh.y);
                    mma16816(acc[1][n], alo1.x, alo1.y, alo1.z, alo1.w, bh.x, bh.y);
                    mma16816(acc[1][n], ahi1.x, ahi1.y, ahi1.z, ahi1.w, bl.x, bl.y);
                }
            }
        }
        if (s + 1 < nst) cp_wait<0>();
        __syncthreads();
    }

    #pragma unroll
    for (int q = 0; q < 2; q++) {
        #pragma unroll
        for (int n = 0; n < NN; n++) {
            int t = t0 + wt*(TT/2) + n*8 + (lane & 3)*2;
            #pragma unroll
            for (int h = 0; h < 2; h++) {
                int co = co0 + wco*32 + q*16 + (lane >> 2) + h*8;
                float sc = scale ? scale[co] : 1.f;
                float bb = bias  ? bias[co]  : 0.f;
                float x0 = acc[q][n][2*h]   * sc + bb;
                float x1 = acc[q][n][2*h+1] * sc + bb;
                if (dorelu) {
                    x0 = x0 >= 0.f ? x0 : NEG*x0;
                    x1 = x1 >= 0.f ? x1 : NEG*x1;
                }
                if (addb) {
                    long obase = ((long)b*CO + co) * Lout + t;
                    float2 a = *(const float2*)&addb[obase];
                    x0 += a.x; x1 += a.y;
                }
                if (outF) {
                    long obase = ((long)b*CO + co) * Lout + t;
                    *(float2*)&outF[obase] = make_float2(x0, x1);
                }
                if (outHi) {
                    float p0 = __shfl_xor_sync(0xffffffffu, x0, 4);
                    float p1 = __shfl_xor_sync(0xffffffffu, x1, 4);
                    if (!(lane & 4)) {
                        unsigned a0h, a0l, b0h, b0l, a1h, a1l, b1h, b1l;
                        split_bf16(x0, a0h, a0l); split_bf16(p0, b0h, b0l);
                        split_bf16(x1, a1h, a1l); split_bf16(p1, b1h, b1l);
                        long pb = ((long)b*(CO >> 1) + (co >> 1))*Lout + t;
                        *(uint2*)&outHi[pb] = make_uint2(a0h | (b0h << 16), a1h | (b1h << 16));
                        *(uint2*)&outLo[pb] = make_uint2(a0l | (b0l << 16), a1l | (b1l << 16));
                    }
                }
                if (poolHi) {
                    float avg = 0.5f*(x0 + x1);
                    float pav = __shfl_xor_sync(0xffffffffu, avg, 4);
                    if (!(lane & 4)) {
                        unsigned ah, al, ph, pl;
                        split_bf16(avg, ah, al); split_bf16(pav, ph, pl);
                        long pb = ((long)b*(CO >> 1) + (co >> 1))*(Lout >> 1) + (t >> 1);
                        poolHi[pb] = ah | (ph << 16);
                        poolLo[pb] = al | (pl << 16);
                    }
                }
            }
        }
    }
}

template<int KW, int STRIDE, int TT, int CB2>
static void launch_conv(dim3 grid,
    const unsigned* wf, const unsigned* inHi, const unsigned* inLo,
    const float* scale, const float* bias, const float* addb,
    float* outF, unsigned* outHi, unsigned* outLo, unsigned* poolHi, unsigned* poolLo,
    int CI, int CO, int Lin, int Lout, int pad, int dorelu, long inBS)
{
    conv_mma<KW,STRIDE,TT,CB2><<<grid, 256>>>(wf, inHi, inLo, scale, bias, addb,
        outF, outHi, outLo, poolHi, poolLo, CI, CO, Lin, Lout, pad, dorelu, inBS);
}

// ---------------- fused rc2 (KW=9,s=1) + rid (KW=1), cp.async staging ----------------
template<int TT, int CB2>
__global__ void __launch_bounds__(256, 2) conv_mma_fused(
    const unsigned* __restrict__ wf9, const unsigned* __restrict__ wf1,
    const unsigned* __restrict__ bHi, const unsigned* __restrict__ bLo,
    const unsigned* __restrict__ pHi, const unsigned* __restrict__ pLo,
    const float* __restrict__ scale, const float* __restrict__ bias,
    unsigned* __restrict__ outHi, unsigned* __restrict__ outLo,
    unsigned* __restrict__ poolHi, unsigned* __restrict__ poolLo,
    int Lh, long inBS)
{
    constexpr int WIN = TT + 8;
    constexpr int NN  = TT / 16;
    constexpr int W   = CB2*10;
    __shared__ __align__(16) unsigned sBH[2][WIN][W], sBL[2][WIN][W];
    __shared__ __align__(16) unsigned sPH[2][TT][W],  sPL[2][TT][W];

    const int tid  = threadIdx.x;
    const int lane = tid & 31;
    const int wid  = tid >> 5;
    const int wco  = wid & 3;
    const int wt   = wid >> 2;
    const int t0   = blockIdx.x * TT;
    const int co0  = blockIdx.y * 128;
    const int b    = blockIdx.z;
    const int NCH  = 16;
    const int nst  = NCH / CB2;
    const long ct0 = (co0 >> 4) + wco*2;
    const unsigned* bHib = bHi + (long)b * inBS;
    const unsigned* bLob = bLo + (long)b * inBS;
    const unsigned* pHib = pHi + (long)b * inBS;
    const unsigned* pLob = pLo + (long)b * inBS;

    float acc9[2][NN][4] = {};
    float acc1[2][NN][4] = {};

    auto stage = [&](int buf, int grp) {
        int cp0 = grp * CB2 * 8;
        for (int idx = tid; idx < CB2*8*WIN; idx += 256) {
            int c2 = idx / (8*WIN);
            int rem = idx - c2*8*WIN;
            int pr = rem / WIN, pos = rem - pr*WIN;
            int j = c2*10 + ((pr < 4) ? (2*pr) : (2*(pr-4)+1));
            long row = (long)(cp0 + c2*8 + pr)*Lh;
            int g = t0 - 4 + pos;
            bool ok = (g >= 0 && g < Lh);
            long gi = row + (ok ? g : 0);
            cp4(&sBH[buf][pos][j], bHib + gi, ok);
            cp4(&sBL[buf][pos][j], bLob + gi, ok);
            if (pos < TT) {
                cp4(&sPH[buf][pos][j], pHib + row + t0 + pos, true);
                cp4(&sPL[buf][pos][j], pLob + row + t0 + pos, true);
            }
        }
        cp_commit();
    };

    stage(0, 0);
    cp_wait<0>();
    __syncthreads();
    for (int s = 0; s < nst; s++) {
        int cur = s & 1;
        if (s + 1 < nst) stage(cur ^ 1, s + 1);
        #pragma unroll
        for (int c2 = 0; c2 < CB2; c2++) {
            int ch = s*CB2 + c2;
            #pragma unroll
            for (int k = 0; k < 9; k++) {
                const uint4* af0 = (const uint4*)(wf9 + (((ct0*NCH + ch)*9 + k) << 8) + (lane << 3));
                const uint4* af1 = (const uint4*)(wf9 + ((((ct0+1)*NCH + ch)*9 + k) << 8) + (lane << 3));
                uint4 ahi0 = af0[0], alo0 = af0[1];
                uint4 ahi1 = af1[0], alo1 = af1[1];
                #pragma unroll
                for (int n = 0; n < NN; n++) {
                    int tl = wt*(TT/2) + n*8 + (lane >> 2);
                    int pos = tl + k;
                    int j2 = c2*10 + (lane & 3)*2;
                    uint2 bh = *(const uint2*)&sBH[cur][pos][j2];
                    uint2 bl = *(const uint2*)&sBL[cur][pos][j2];
                    mma16816(acc9[0][n], ahi0.x, ahi0.y, ahi0.z, ahi0.w, bh.x, bh.y);
                    mma16816(acc9[0][n], alo0.x, alo0.y, alo0.z, alo0.w, bh.x, bh.y);
                    mma16816(acc9[0][n], ahi0.x, ahi0.y, ahi0.z, ahi0.w, bl.x, bl.y);
                    mma16816(acc9[1][n], ahi1.x, ahi1.y, ahi1.z, ahi1.w, bh.x, bh.y);
                    mma16816(acc9[1][n], alo1.x, alo1.y, alo1.z, alo1.w, bh.x, bh.y);
                    mma16816(acc9[1][n], ahi1.x, ahi1.y, ahi1.z, ahi1.w, bl.x, bl.y);
                }
            }
            {
                const uint4* af0 = (const uint4*)(wf1 + (((ct0*NCH + ch)) << 8) + (lane << 3));
                const uint4* af1 = (const uint4*)(wf1 + ((((ct0+1)*NCH + ch)) << 8) + (lane << 3));
                uint4 ahi0 = af0[0], alo0 = af0[1];
                uint4 ahi1 = af1[0], alo1 = af1[1];
                #pragma unroll
                for (int n = 0; n < NN; n++) {
                    int pos = wt*(TT/2) + n*8 + (lane >> 2);
                    int j2 = c2*10 + (lane & 3)*2;
                    uint2 bh = *(const uint2*)&sPH[cur][pos][j2];
                    uint2 bl = *(const uint2*)&sPL[cur][pos][j2];
                    mma16816(acc1[0][n], ahi0.x, ahi0.y, ahi0.z, ahi0.w, bh.x, bh.y);
                    mma16816(acc1[0][n], alo0.x, alo0.y, alo0.z, alo0.w, bh.x, bh.y);
                    mma16816(acc1[0][n], ahi0.x, ahi0.y, ahi0.z, ahi0.w, bl.x, bl.y);
                    mma16816(acc1[1][n], ahi1.x, ahi1.y, ahi1.z, ahi1.w, bh.x, bh.y);
                    mma16816(acc1[1][n], alo1.x, alo1.y, alo1.z, alo1.w, bh.x, bh.y);
                    mma16816(acc1[1][n], ahi1.x, ahi1.y, ahi1.z, ahi1.w, bl.x, bl.y);
                }
            }
        }
        if (s + 1 < nst) cp_wait<0>();
        __syncthreads();
    }

    #pragma unroll
    for (int q = 0; q < 2; q++) {
        #pragma unroll
        for (int n = 0; n < NN; n++) {
            int t = t0 + wt*(TT/2) + n*8 + (lane & 3)*2;
            #pragma unroll
            for (int h = 0; h < 2; h++) {
                int co = co0 + wco*32 + q*16 + (lane >> 2) + h*8;
                float sc = scale[co];
                float bb = bias[co];
                float x0 = acc9[q][n][2*h]   * sc + bb;
                float x1 = acc9[q][n][2*h+1] * sc + bb;
                x0 = x0 >= 0.f ? x0 : NEG*x0;
                x1 = x1 >= 0.f ? x1 : NEG*x1;
                x0 += acc1[q][n][2*h];
                x1 += acc1[q][n][2*h+1];
                float p0 = __shfl_xor_sync(0xffffffffu, x0, 4);
                float p1 = __shfl_xor_sync(0xffffffffu, x1, 4);
                float avg = 0.5f*(x0 + x1);
                float pav = __shfl_xor_sync(0xffffffffu, avg, 4);
                if (!(lane & 4)) {
                    unsigned a0h, a0l, b0h, b0l, a1h, a1l, b1h, b1l;
                    split_bf16(x0, a0h, a0l); split_bf16(p0, b0h, b0l);
                    split_bf16(x1, a1h, a1l); split_bf16(p1, b1h, b1l);
                    long pb = ((long)b*128 + (co >> 1))*Lh + t;
                    *(uint2*)&outHi[pb] = make_uint2(a0h | (b0h << 16), a1h | (b1h << 16));
                    *(uint2*)&outLo[pb] = make_uint2(a0l | (b0l << 16), a1l | (b1l << 16));
                    unsigned ah, al, ph, pl;
                    split_bf16(avg, ah, al); split_bf16(pav, ph, pl);
                    long qb = ((long)b*128 + (co >> 1))*(Lh >> 1) + (t >> 1);
                    poolHi[qb] = ah | (ph << 16);
                    poolLo[qb] = al | (pl << 16);
                }
            }
        }
    }
}

// ---------------- scalar implicit-GEMM conv1d (CI=1 layers) ----------------
template<int KW, int STRIDE, int CB>
__global__ void __launch_bounds__(256, 2) conv_gemm(
    const float* __restrict__ wT, const float* __restrict__ in,
    const float* __restrict__ scale, const float* __restrict__ bias,
    float* __restrict__ out,
    int CI, int CO, int Lin, int Lout, int pad, int dorelu, long inBS)
{
    constexpr int WIN  = 64*STRIDE + KW - 1;
    constexpr int WINP = (WIN + 11) & ~3;
    constexpr int RW   = 3*STRIDE + KW;
    constexpr int NV   = (RW + 3) / 4;
    __shared__ __align__(16) float sW[2][CB*KW*64];
    __shared__ __align__(16) float sIn[2][CB][WINP];

    const int tid = threadIdx.x;
    const int tx = tid & 15, ty = tid >> 4;
    const int t0 = blockIdx.x * 64, co0 = blockIdx.y * 64;
    const int b  = blockIdx.z;
    const float* inb = in + (long)b * inBS;
    const long wstride = (long)KW * 64;
    const float* wbase = wT + (long)blockIdx.y * CI * wstride;

    ull acc01[4], acc23[4];
    #pragma unroll
    for (int j = 0; j < 4; j++) { acc01[j] = 0ull; acc23[j] = 0ull; }

    const int nst = CI / CB;
    auto stage = [&](int buf, int cib) {
        const float4* ws = (const float4*)(wbase + (long)cib * wstride);
        float4* wd = (float4*)sW[buf];
        for (int idx = tid; idx < CB*KW*16; idx += 256) wd[idx] = ws[idx];
        for (int idx = tid; idx < CB*WIN; idx += 256) {
            int c = idx / WIN, w = idx - c*WIN;
            int g = t0*STRIDE - pad + w;
            sIn[buf][c][w] = (g >= 0 && g < Lin) ? __ldg(&inb[(long)(cib+c)*Lin + g]) : 0.f;
        }
    };

    stage(0, 0);
    __syncthreads();
    for (int s = 0; s < nst; s++) {
        int cur = s & 1;
        if (s + 1 < nst) stage(cur ^ 1, (s + 1) * CB);
        #pragma unroll
        for (int c = 0; c < CB; c++) {
            float4 wv4[NV];
            const float4* ip = (const float4*)&sIn[cur][c][tx*4*STRIDE];
            #pragma unroll
            for (int v = 0; v < NV; v++) wv4[v] = ip[v];
            const float* wfp = (const float*)wv4;
            ull bc[RW];
            #pragma unroll
            for (int m = 0; m < RW; m++) bc[m] = pk2(wfp[m], wfp[m]);
            const float* wrow = sW[cur] + c*KW*64 + ty*4;
            #pragma unroll
            for (int k = 0; k < KW; k++) {
                ulonglong2 wv = *(const ulonglong2*)(wrow + k*64);
                #pragma unroll
                for (int j = 0; j < 4; j++) {
                    acc01[j] = ffma2(wv.x, bc[j*STRIDE + k], acc01[j]);
                    acc23[j] = ffma2(wv.y, bc[j*STRIDE + k], acc23[j]);
                }
            }
        }
        __syncthreads();
    }

    float r[4][4];
    #pragma unroll
    for (int j = 0; j < 4; j++) { upk2(acc01[j], r[0][j], r[1][j]); upk2(acc23[j], r[2][j], r[3][j]); }
    #pragma unroll
    for (int i = 0; i < 4; i++) {
        int co = co0 + ty*4 + i;
        float sc = scale ? scale[co] : 1.f;
        float bb = bias  ? bias[co]  : 0.f;
        long obase = ((long)b*CO + co) * Lout + t0 + tx*4;
        float4 v;
        v.x = r[i][0]*sc + bb; v.y = r[i][1]*sc + bb;
        v.z = r[i][2]*sc + bb; v.w = r[i][3]*sc + bb;
        if (dorelu) {
            v.x = v.x >= 0.f ? v.x : NEG*v.x; v.y = v.y >= 0.f ? v.y : NEG*v.y;
            v.z = v.z >= 0.f ? v.z : NEG*v.z; v.w = v.w >= 0.f ? v.w : NEG*v.w;
        }
        *(float4*)&out[obase] = v;
    }
}

// ---------------- attention per (batch, head): writes ATT pair planes ----------------
__global__ void __launch_bounds__(128) attn_kernel(const float* __restrict__ qkv,
                                                   unsigned* __restrict__ ohi,
                                                   unsigned* __restrict__ olo)
{
    __shared__ float q[32][64], kk[32][64], vv[32][64];
    __shared__ float att[64][65];
    int bh = blockIdx.x; int b = bh >> 3, h = bh & 7;
    const float* base = qkv + (long)b*768*64 + (long)h*32*64;
    int tid = threadIdx.x;
    for (int idx = tid; idx < 2048; idx += 128) {
        int d = idx >> 6, s = idx & 63;
        q [d][s] = base[d*64 + s];
        kk[d][s] = base[256*64 + d*64 + s];
        vv[d][s] = base[512*64 + d*64 + s];
    }
    __syncthreads();
    for (int e = tid; e < 4096; e += 128) {
        int qs = e >> 6, ks = e & 63;
        float s = 0.f;
        #pragma unroll
        for (int d = 0; d < 32; d++) s = fmaf(q[d][qs], kk[d][ks], s);
        att[qs][ks] = s * 0.17677669529663687f;
    }
    __syncthreads();
    if (tid < 64) {
        float m = -1e30f;
        for (int ks = 0; ks < 64; ks++) m = fmaxf(m, att[tid][ks]);
        float sum = 0.f;
        for (int ks = 0; ks < 64; ks++) { float e = expf(att[tid][ks] - m); att[tid][ks] = e; sum += e; }
        float inv = 1.f / sum;
        for (int ks = 0; ks < 64; ks++) att[tid][ks] *= inv;
    }
    __syncthreads();
    for (int e = tid; e < 1024; e += 128) {
        int m = e >> 6, qs = e & 63;
        float s0 = 0.f, s1 = 0.f;
        #pragma unroll
        for (int ks = 0; ks < 64; ks++) {
            float a = att[qs][ks];
            s0 = fmaf(a, vv[2*m][ks],   s0);
            s1 = fmaf(a, vv[2*m+1][ks], s1);
        }
        unsigned h0, l0, h1, l1;
        split_bf16(s0, h0, l0);
        split_bf16(s1, h1, l1);
        long idx = ((long)b*128 + h*16 + m)*64 + qs;
        ohi[idx] = h0 | (h1 << 16);
        olo[idx] = l0 | (l1 << 16);
    }
}

__global__ void max_t_kernel(const float* __restrict__ in, float* __restrict__ out)
{
    int b = blockIdx.x, c = threadIdx.x;
    const float* r = in + ((long)b*256 + c) * 64;
    float m = r[0];
    #pragma unroll
    for (int t = 1; t < 64; t++) m = fmaxf(m, r[t]);
    out[b*256 + c] = m;
}

__global__ void group_max_kernel(const float* __restrict__ in, float* __restrict__ out, int GS)
{
    int row = blockIdx.x; int g = threadIdx.x; int G = blockDim.x;
    const float* r = in + (long)row*G*GS + (long)g*GS;
    float m = r[0];
    for (int j = 1; j < GS; j++) m = fmaxf(m, r[j]);
    out[(long)row*G + g] = m;
}

// ---------------- dense: one warp per (batch, output) ----------------
__global__ void __launch_bounds__(256) dense_kernel(const float* __restrict__ in,
                                                    const float* __restrict__ w,
                                                    const float* __restrict__ bias,
                                                    float* __restrict__ out,
                                                    int IN, int OUT, int dorelu)
{
    int wid = threadIdx.x >> 5, lane = threadIdx.x & 31;
    int gid = blockIdx.x*8 + wid;
    int b = gid / OUT, o = gid - b*OUT;
    if (b >= 64) return;
    const float* iv = in + (long)b*IN;
    const float* wr = w + (long)o*IN;
    float s = 0.f;
    for (int i = lane; i < IN; i += 32) s = fmaf(iv[i], wr[i], s);
    #pragma unroll
    for (int off = 16; off > 0; off >>= 1) s += __shfl_down_sync(0xffffffffu, s, off);
    if (lane == 0) {
        if (bias) s += bias[o];
        if (dorelu) s = (s >= 0.f) ? s : NEG*s;
        out[b*OUT + o] = s;
    }
}

__global__ void twiddle_kernel()
{
    int i = blockIdx.x*256 + threadIdx.x;
    if (i < 4096) {
        double a = -2.0 * 3.14159265358979323846 * (double)i / 4096.0;
        g_tw[i] = make_float2((float)cos(a), (float)sin(a));
    }
}

__global__ void __launch_bounds__(256) fft_freq_kernel(const float* __restrict__ x,
                                                       const float* __restrict__ fw,
                                                       const float* __restrict__ fb,
                                                       float* __restrict__ out)
{
    __shared__ float2 stw[4096];
    __shared__ float smag[256];
    __shared__ float sred[256];
    int b = blockIdx.x, tid = threadIdx.x;
    for (int i = tid; i < 4096; i += 256) stw[i] = g_tw[i];
    const float* xr = x + ((long)b*12 + 1) * 4096;
    __syncthreads();
    int k = 50 + tid;
    float re0 = 0.f, im0 = 0.f, re1 = 0.f, im1 = 0.f;
    for (int n = 0; n < 4096; n += 4) {
        float4 xv = *(const float4*)&xr[n];
        int i0 = (k*n) & 4095;
        int i1 = (i0 + k) & 4095;
        int i2 = (i0 + 2*k) & 4095;
        int i3 = (i0 + 3*k) & 4095;
        float2 c0 = stw[i0], c1 = stw[i1], c2 = stw[i2], c3 = stw[i3];
        re0 = fmaf(xv.x, c0.x, re0); im0 = fmaf(xv.x, c0.y, im0);
        re1 = fmaf(xv.y, c1.x, re1); im1 = fmaf(xv.y, c1.y, im1);
        re0 = fmaf(xv.z, c2.x, re0); im0 = fmaf(xv.z, c2.y, im0);
        re1 = fmaf(xv.w, c3.x, re1); im1 = fmaf(xv.w, c3.y, im1);
    }
    float re = re0 + re1, im = im0 + im1;
    float mag = sqrtf(re*re + im*im);
    smag[tid] = mag; sred[tid] = mag;
    __syncthreads();
    for (int s = 128; s > 0; s >>= 1) {
        if (tid < s) sred[tid] = fmaxf(sred[tid], sred[tid+s]);
        __syncthreads();
    }
    float mx = sred[0];
    smag[tid] = (mx > 0.f) ? mag/mx : mag;
    __syncthreads();
    if (tid < 32) {
        float s = fb[tid];
        const float* wr = fw + tid*256;
        for (int j = 0; j < 256; j++) s = fmaf(smag[j], wr[j], s);
        out[b*32 + tid] = (s >= 0.f) ? s : NEG*s;
    }
}

__global__ void final_kernel(const float* __restrict__ xm, const float* __restrict__ l,
                             const float* __restrict__ fq, const float* __restrict__ f2,
                             const float* __restrict__ p2, const float* __restrict__ fcw,
                             const float* __restrict__ fcb, float* __restrict__ out)
{
    __shared__ float comb[396];
    int b = blockIdx.x, tid = threadIdx.x;
    for (int i = tid; i < 256; i += 128) comb[i] = xm[b*256 + i];
    if (tid < 12) comb[256 + tid] = l[b*12 + tid];
    if (tid < 32) comb[268 + tid] = fq[b*32 + tid];
    if (tid < 64) comb[300 + tid] = f2[b*64 + tid];
    if (tid < 32) comb[364 + tid] = p2[b*32 + tid];
    __syncthreads();
    if (tid < 27) {
        float s = fcb[tid];
        const float* wr = fcw + tid*396;
        for (int j = 0; j < 396; j++) s = fmaf(comb[j], wr[j], s);
        out[b*27 + tid] = s;
        out[64*27 + b*27 + tid] = 1.f / (1.f + expf(-s));
    }
}

// ---------------- host launch ----------------
extern "C" void kernel_launch(void* const* d_in, const int* in_sizes, int n_in,
                              void* d_out, int out_size)
{
    (void)in_sizes; (void)n_in; (void)out_size;
    const float* x      = (const float*)d_in[0];
    const float* l      = (const float*)d_in[1];
    const float* conv_w = (const float*)d_in[2];
    const float* bn0    = (const float*)d_in[3];
    const float* rc1    = (const float*)d_in[4];
    const float* rbn1   = (const float*)d_in[5];
    const float* rc2    = (const float*)d_in[6];
    const float* rbn2   = (const float*)d_in[7];
    const float* rid    = (const float*)d_in[8];
    const float* miw    = (const float*)d_in[9];
    const float* mib    = (const float*)d_in[10];
    const float* mow    = (const float*)d_in[11];
    const float* mob    = (const float*)d_in[12];
    const float* fw     = (const float*)d_in[13];
    const float* fbv    = (const float*)d_in[14];
    const float* fbn    = (const float*)d_in[15];
    const float* pw     = (const float*)d_in[16];
    const float* pbv    = (const float*)d_in[17];
    const float* pbn    = (const float*)d_in[18];
    const float* wflut2 = (const float*)d_in[19];
    const float* wpvc2  = (const float*)d_in[20];
    const float* freqw  = (const float*)d_in[21];
    const float* freqb  = (const float*)d_in[22];
    const float* fcw    = (const float*)d_in[23];
    const float* fcb    = (const float*)d_in[24];

    unsigned *A, *Bf, *P0, *ATT, *WF;
    float *C, *S, *QKV, *HM, *XM, *FV, *PV, *F2, *P2, *FQ, *BN, *WT;
    cudaGetSymbolAddress((void**)&A,   g_bufA);
    cudaGetSymbolAddress((void**)&Bf,  g_bufB);
    cudaGetSymbolAddress((void**)&P0,  g_bufP);
    cudaGetSymbolAddress((void**)&C,   g_bufC);
    cudaGetSymbolAddress((void**)&S,   g_bufS);
    cudaGetSymbolAddress((void**)&QKV, g_qkv);
    cudaGetSymbolAddress((void**)&ATT, g_att);
    cudaGetSymbolAddress((void**)&HM,  g_hm);
    cudaGetSymbolAddress((void**)&XM,  g_xmain);
    cudaGetSymbolAddress((void**)&FV,  g_fvec);
    cudaGetSymbolAddress((void**)&PV,  g_pvec);
    cudaGetSymbolAddress((void**)&F2,  g_f2);
    cudaGetSymbolAddress((void**)&P2,  g_p2);
    cudaGetSymbolAddress((void**)&FQ,  g_freq);
    cudaGetSymbolAddress((void**)&BN,  g_bn);
    cudaGetSymbolAddress((void**)&WT,  g_wT);
    cudaGetSymbolAddress((void**)&WF,  g_wf);

    float* S0 = S;
    float* S1 = S + 64L*64*2048;

    unsigned* XP = (unsigned*)C;   // conv0 packed input planes
    unsigned* P1 = (unsigned*)C;   // P pong (free after last separate-rid layer)

    // side streams (created once; identical work every call)
    static cudaStream_t sA = 0, sB = 0;
    static cudaEvent_t evFork = 0, evJoinA = 0, evJoinB = 0;
    if (!evFork) {
        cudaStreamCreateWithFlags(&sA, cudaStreamNonBlocking);
        cudaStreamCreateWithFlags(&sB, cudaStreamNonBlocking);
        cudaEventCreateWithFlags(&evFork,  cudaEventDisableTiming);
        cudaEventCreateWithFlags(&evJoinA, cudaEventDisableTiming);
        cudaEventCreateWithFlags(&evJoinB, cudaEventDisableTiming);
    }

    prep_kernel<<<1, 256>>>(bn0, rbn1, rbn2, fbn, fbv, pbn, pbv);
    twiddle_kernel<<<16, 256>>>();
    pack_x_kernel<<<8192, 256>>>(x, XP, XP + PL_X);

    auto wt = [&](const float* src, long off, int CO, int CI, int KW) {
        long tot = (long)CO*CI*KW;
        wtrans_kernel<<<(unsigned)((tot + 255)/256), 256>>>(src, WT + off, CI, KW, tot);
    };
    wt(fw, O_FLUT, 64, 1, 15);
    wt(pw, O_PVC,  64, 1, 9);

    // fork side paths (depend only on prep/twiddle/wtrans)
    cudaEventRecord(evFork, 0);
    cudaStreamWaitEvent(sA, evFork, 0);
    cudaStreamWaitEvent(sB, evFork, 0);

    // ----- side stream A: FLUT path -----
    conv_gemm<15,2,1><<<dim3(32,1,64), 256, 0, sA>>>(WT+O_FLUT, x + 4096, BN+5632, BN+5696, S0,
                                                     1, 64, 4096, 2048, 7, 1, 12L*4096);
    group_max_kernel<<<64*64, 64, 0, sA>>>(S0, FV, 32);
    dense_kernel<<<512, 256, 0, sA>>>(FV, wflut2, nullptr, F2, 4096, 64, 1);
    cudaEventRecord(evJoinA, sA);

    // ----- side stream B: PVC path + FFT -----
    conv_gemm<9,2,1><<<dim3(32,1,64), 256, 0, sB>>>(WT+O_PVC, x + 4096, BN+5760, BN+5824, S1,
                                                    1, 64, 4096, 2048, 4, 1, 12L*4096);
    group_max_kernel<<<64*64, 32, 0, sB>>>(S1, PV, 64);
    dense_kernel<<<256, 256, 0, sB>>>(PV, wpvc2, nullptr, P2, 2048, 32, 1);
    fft_freq_kernel<<<64, 256, 0, sB>>>(x, freqw, freqb, FQ);
    cudaEventRecord(evJoinB, sB);

    // ----- main chain (stream 0) -----
    auto wfp = [&](const float* src, long off, int CO, int CIsrc, int CIpad, int KW) {
        long tot = (long)(CO/16)*(CIpad/16)*KW*128;
        wfrag_kernel<<<(unsigned)((tot + 255)/256), 256>>>(src, WF + off, CIsrc, KW, CIpad/16, tot);
    };
    for (int i = 0; i < 5; i++) {
        wfp(rc1 + (long)i*256*256*9, WF_RC1 + (long)i*589824, 256, 256, 256, 9);
        wfp(rc2 + (long)i*256*256*9, WF_RC2 + (long)i*589824, 256, 256, 256, 9);
        wfp(rid + (long)i*256*256,   WF_RID + (long)i*65536,  256, 256, 256, 1);
    }
    wfp(miw,    WF_MHAIN,  768, 256, 256, 1);
    wfp(mow,    WF_MHAOUT, 256, 256, 256, 1);
    wfp(conv_w, WF_CONV0,  256,  12,  16, 15);

    launch_conv<15,2,64,1>(dim3(32,2,64), WF+WF_CONV0, XP, XP + PL_X, BN+0, BN+256, nullptr,
                           nullptr, A, A + PL_A, P0, P0 + PL_P,
                           16, 256, 4096, 2048, 7, 1, 8L*4096);

    unsigned* Pcur = P0;
    unsigned* Palt = P1;
    int L = 2048;
    for (int i = 0; i < 5; i++) {
        int Lh = L/2;
        if (Lh >= 256) {
            launch_conv<9,2,128,1>(dim3(Lh/128,2,64), WF+WF_RC1 + (long)i*589824, A, A + PL_A,
                BN+512+i*256, BN+1792+i*256, nullptr, nullptr, Bf, Bf + PL_B, nullptr, nullptr,
                256, 256, L, Lh, 4, 1, 128L*L);
            launch_conv<1,1,128,2>(dim3(Lh/128,2,64), WF+WF_RID + (long)i*65536, Pcur, Pcur + PL_P,
                nullptr, nullptr, nullptr, C, nullptr, nullptr, nullptr, nullptr,
                256, 256, Lh, Lh, 0, 0, 128L*Lh);
            launch_conv<9,1,128,2>(dim3(Lh/128,2,64), WF+WF_RC2 + (long)i*589824, Bf, Bf + PL_B,
                BN+3072+i*256, BN+4352+i*256, C, nullptr, A, A + PL_A, Pcur, Pcur + PL_P,
                256, 256, Lh, Lh, 4, 1, 128L*Lh);
        } else {
            if (Lh == 128)
                launch_conv<9,2,64,1>(dim3(2,2,64), WF+WF_RC1 + (long)i*589824, A, A + PL_A,
                    BN+512+i*256, BN+1792+i*256, nullptr, nullptr, Bf, Bf + PL_B, nullptr, nullptr,
                    256, 256, L, Lh, 4, 1, 128L*L);
            else
                launch_conv<9,2,32,1>(dim3(2,2,64), WF+WF_RC1 + (long)i*589824, A, A + PL_A,
                    BN+512+i*256, BN+1792+i*256, nullptr, nullptr, Bf, Bf + PL_B, nullptr, nullptr,
                    256, 256, L, Lh, 4, 1, 128L*L);
            conv_mma_fused<64,2><<<dim3(Lh/64,2,64), 256>>>(
                WF+WF_RC2 + (long)i*589824, WF+WF_RID + (long)i*65536,
                Bf, Bf + PL_B, Pcur, Pcur + PL_P,
                BN+3072+i*256, BN+4352+i*256,
                A, A + PL_A, Palt, Palt + PL_P, Lh, 128L*Lh);
            unsigned* tmp = Pcur; Pcur = Palt; Palt = tmp;
        }
        L = Lh;
    }

    // MHA
    launch_conv<1,1,64,2>(dim3(1,6,64), WF+WF_MHAIN, A, A + PL_A, nullptr, mib, nullptr,
                          QKV, nullptr, nullptr, nullptr, nullptr,
                          256, 768, 64, 64, 0, 0, 128L*64);
    attn_kernel<<<512, 128>>>(QKV, ATT, ATT + PL_ATT);
    launch_conv<1,1,64,2>(dim3(1,2,64), WF+WF_MHAOUT, ATT, ATT + PL_ATT, nullptr, mob, nullptr,
                          HM, nullptr, nullptr, nullptr, nullptr,
                          256, 256, 64, 64, 0, 0, 128L*64);
    max_t_kernel<<<64, 256>>>(HM, XM);

    // join side paths before final concat
    cudaStreamWaitEvent(0, evJoinA, 0);
    cudaStreamWaitEvent(0, evJoinB, 0);

    // concat + FC + sigmoid
    final_kernel<<<64, 128>>>(XM, l, FQ, F2, P2, fcw, fcb, (float*)d_out);
}